// round 7
// baseline (speedup 1.0000x reference)
#include <cuda_runtime.h>
#include <math.h>
#include <stdint.h>

#define BB 8
#define NQ 1024
#define NK 256
#define HH 8
#define DF 528
#define DFP 576
#define DX 544

typedef unsigned long long u64;
typedef unsigned int u32;

__constant__ int c_cg[11]    = {0,1,1,1,2,2,2,3,3,3,3};
__constant__ int c_comps[11] = {0,2,3,4,8,9,10,14,11,12,13};
__constant__ int c_grade[16] = {0,1,1,1,1,2,2,2,2,2,2,3,3,3,3,4};

__device__ float g_WqT [5*48*384];
__device__ float g_WkvT[5*48*768];
__device__ float g_WoT [5*384*48];
__device__ float g_sp  [8];
__device__ float g_xfeat [(size_t)BB*NQ*DX];
__device__ float g_M     [(size_t)BB*HH*NK*DX];
__device__ float g_kfeatT[(size_t)BB*HH*NK*DFP];
__device__ float g_vtmp  [(size_t)BB*HH*48*16*NK];
__device__ float g_vprojT[(size_t)BB*768*2048];
__device__ float g_attn  [(size_t)BB*NQ*2048];

__device__ __forceinline__ u64 pk2(float lo, float hi){
    u64 u; asm("mov.b64 %0,{%1,%2};" : "=l"(u) : "f"(lo), "f"(hi)); return u;
}
__device__ __forceinline__ void upk2(u64 u, float& lo, float& hi){
    asm("mov.b64 {%0,%1},%2;" : "=f"(lo), "=f"(hi) : "l"(u));
}
__device__ __forceinline__ u64 f2fma(u64 a, u64 b, u64 c){
    u64 d; asm("fma.rn.f32x2 %0,%1,%2,%3;" : "=l"(d) : "l"(a), "l"(b), "l"(c)); return d;
}
__device__ __forceinline__ u32 cvt_tf32(float x){
    u32 r; asm("cvt.rna.tf32.f32 %0,%1;" : "=r"(r) : "f"(x)); return r;
}
__device__ __forceinline__ float rnd_tf32(float x){ return __uint_as_float(cvt_tf32(x)); }
__device__ __forceinline__ void mma168(float* d, const u32* a, const u32* b){
    asm volatile("mma.sync.aligned.m16n8k8.row.col.f32.tf32.tf32.f32 "
        "{%0,%1,%2,%3},{%4,%5,%6,%7},{%8,%9},{%0,%1,%2,%3};"
        : "+f"(d[0]), "+f"(d[1]), "+f"(d[2]), "+f"(d[3])
        : "r"(a[0]), "r"(a[1]), "r"(a[2]), "r"(a[3]), "r"(b[0]), "r"(b[1]));
}

// ===================== K0: weight transposes + softplus =====================
__global__ void k0_prep(const float* __restrict__ Wq, const float* __restrict__ Wkv,
                        const float* __restrict__ Wo, const float* __restrict__ daa){
    int stride = gridDim.x * blockDim.x;
    int gid = blockIdx.x * blockDim.x + threadIdx.x;
    for (int idx = gid; idx < 5*384*48; idx += stride){
        int g = idx/(384*48), rem = idx%(384*48), o = rem/48, i = rem%48;
        g_WqT[(g*48+i)*384+o] = Wq[idx];
    }
    for (int idx = gid; idx < 5*768*48; idx += stride){
        int g = idx/(768*48), rem = idx%(768*48), o = rem/48, i = rem%48;
        g_WkvT[(g*48+i)*768+o] = Wkv[idx];
    }
    for (int idx = gid; idx < 5*48*384; idx += stride){
        int g = idx/(48*384), rem = idx%(48*384), o = rem/384, i = rem%384;
        g_WoT[(g*384+i)*48+o] = Wo[idx];
    }
    if (gid < 8){
        float x = daa[gid];
        g_sp[gid] = (x > 20.f) ? x : log1pf(expf(x));
    }
}

// ========== K1a: kv projection, 16 keys/block -> kfeatT(row-major)/vtmp =====
__global__ void __launch_bounds__(256) k1a_kv(const float* __restrict__ vision,
                                              const float* __restrict__ bkv){
    extern __shared__ float sm1[];
    float* xT  = sm1;           // [(c*48+in)][key16] pad 18
    float* k2s = sm1 + 768*18;  // [h*16+key]
    int b = blockIdx.y, k0 = blockIdx.x*16, t = threadIdx.x;

    for (int idx = t; idx < 16*768; idx += 256){
        int key = idx/768, e = idx - key*768, in = e>>4, c = e&15;
        xT[(c*48+in)*18 + key] = vision[((size_t)(b*NK + k0 + key))*768 + e];
    }
    if (t < 128) k2s[t] = 0.f;
    __syncthreads();

    const float INVS = 0.051031036307982884f;  // 1/sqrt(384)
    const int GR[16] = {0,1,1,1,1,2,2,2,2,2,2,3,3,3,3,4};

    for (int s = 0; s < 3; s++){
        int o = t + 256*s;
        float bias = bkv[o];
        const float* wb = g_WkvT + o;
        for (int kt = 0; kt < 4; kt++){
            u64 acc[2][16];
            #pragma unroll
            for (int kp = 0; kp < 2; kp++){
                acc[kp][0] = pk2(bias, bias);
                #pragma unroll
                for (int c = 1; c < 16; c++) acc[kp][c] = 0ull;
            }
            #pragma unroll 4
            for (int in = 0; in < 48; in++){
                float w0 = wb[(0*48+in)*768], w1 = wb[(1*48+in)*768];
                float w2 = wb[(2*48+in)*768], w3 = wb[(3*48+in)*768];
                float w4 = wb[(4*48+in)*768];
                u64 wv[5] = {pk2(w0,w0), pk2(w1,w1), pk2(w2,w2), pk2(w3,w3), pk2(w4,w4)};
                #pragma unroll
                for (int c = 0; c < 16; c++){
                    const float* xp = xT + (c*48+in)*18 + kt*4;
                    acc[0][c] = f2fma(*(const u64*)(xp    ), wv[GR[c]], acc[0][c]);
                    acc[1][c] = f2fma(*(const u64*)(xp + 2), wv[GR[c]], acc[1][c]);
                }
            }
            if (o < 384){
                int h = o/48, i = o - h*48;
                float sp = g_sp[h], spc = sp*(2.f/48.f);
                size_t rb = (size_t)((b*HH+h)*NK + k0 + kt*4)*DFP;
                const int IC[8] = {0,2,3,4,8,9,10,14};
                #pragma unroll
                for (int js = 0; js < 8; js++)
                    #pragma unroll
                    for (int kp = 0; kp < 2; kp++){
                        float lo, hi; upk2(acc[kp][IC[js]], lo, hi);
                        g_kfeatT[rb + (size_t)(2*kp  )*DFP + js*48+i] = lo*INVS;
                        g_kfeatT[rb + (size_t)(2*kp+1)*DFP + js*48+i] = hi*INVS;
                    }
                const int PC[3] = {11,12,13};
                float s2[4] = {0.f,0.f,0.f,0.f};
                #pragma unroll
                for (int jp = 0; jp < 3; jp++)
                    #pragma unroll
                    for (int kp = 0; kp < 2; kp++){
                        float lo, hi; upk2(acc[kp][PC[jp]], lo, hi);
                        g_kfeatT[rb + (size_t)(2*kp  )*DFP + 384+jp*48+i] = lo*spc;
                        g_kfeatT[rb + (size_t)(2*kp+1)*DFP + 384+jp*48+i] = hi*spc;
                        s2[2*kp] += lo*lo; s2[2*kp+1] += hi*hi;
                    }
                #pragma unroll
                for (int kk = 0; kk < 4; kk++) atomicAdd(&k2s[h*16 + kt*4 + kk], s2[kk]);
            } else {
                int vc = o - 384, h = vc/48, i = vc - h*48;
                float* vb = g_vtmp + (size_t)(((b*HH+h)*48+i)*16)*NK + (k0 + kt*4);
                #pragma unroll
                for (int c = 0; c < 16; c++){
                    *(u64*)&vb[(size_t)c*NK]     = acc[0][c];
                    *(u64*)&vb[(size_t)c*NK + 2] = acc[1][c];
                }
            }
        }
    }
    __syncthreads();
    if (t < 128){
        int h = t>>4, key = t&15;
        g_kfeatT[(size_t)((b*HH+h)*NK + k0 + key)*DFP + 528] = -g_sp[h]*k2s[t]*(1.f/48.f);
    }
}

// ========== K1b: vprojT[b][col768][kh2048] (tf32 pre-rounded) ==============
__global__ void __launch_bounds__(256) k1b_vproj(){
    extern __shared__ float sm2[];
    float* w_s = sm2;            // [g][i*48+o48] 5*2304
    float* v_s = sm2 + 11520;    // [(i*16+c)][key16] pad 18
    int sl = blockIdx.x, h = blockIdx.y, b = blockIdx.z, t = threadIdx.x;

    for (int idx = t; idx < 11520; idx += 256){
        int g = idx/2304, r = idx - g*2304;
        w_s[idx] = g_WoT[(g*384 + h*48)*48 + r];
    }
    int j = sl*256 + t;
    int o48 = j>>4, c = j&15, g = c_grade[c];
    const size_t vbase = (size_t)((b*HH+h)*48)*16*NK;

    for (int kt = 0; kt < 16; kt++){
        __syncthreads();
        for (int idx = t; idx < 12288; idx += 256){
            int key = idx&15, rr = idx>>4;
            v_s[rr*18 + key] = g_vtmp[vbase + (size_t)rr*NK + kt*16 + key];
        }
        __syncthreads();
        u64 acc[8];
        #pragma unroll
        for (int kp = 0; kp < 8; kp++) acc[kp] = 0ull;
        #pragma unroll 4
        for (int i = 0; i < 48; i++){
            float ww = w_s[g*2304 + i*48 + o48];
            u64 w2 = pk2(ww, ww);
            const float* vp = v_s + (i*16+c)*18;
            #pragma unroll
            for (int kp = 0; kp < 8; kp++)
                acc[kp] = f2fma(*(const u64*)(vp + 2*kp), w2, acc[kp]);
        }
        float* dst = g_vprojT + (size_t)(b*768 + j)*2048 + h*NK + kt*16;
        #pragma unroll
        for (int kp = 0; kp < 8; kp++){
            float lo, hi; upk2(acc[kp], lo, hi);
            dst[2*kp]   = rnd_tf32(lo);
            dst[2*kp+1] = rnd_tf32(hi);
        }
    }
}

// ============ K2x: rmsnorm + reorder -> xfeat [row][544] (tf32) =============
__global__ void __launch_bounds__(256) k2x_xfeat(const float* __restrict__ hidden,
                                                 const float* __restrict__ lnw){
    extern __shared__ float sx[];
    float* rows = sx;               // 16*768
    float* rsq  = sx + 16*768;      // 16
    int b = blockIdx.y, q0 = blockIdx.x*16, t = threadIdx.x;
    const float* hrow = hidden + (size_t)(b*NQ+q0)*768;
    for (int idx = t; idx < 16*768; idx += 256) rows[idx] = hrow[idx];
    __syncthreads();
    { int r = t>>4, sub = t&15; float s = 0.f;
      for (int e = sub; e < 768; e += 16){ float v = rows[r*768+e]; s += v*v; }
      s += __shfl_xor_sync(~0u, s, 1);
      s += __shfl_xor_sync(~0u, s, 2);
      s += __shfl_xor_sync(~0u, s, 4);
      s += __shfl_xor_sync(~0u, s, 8);
      if (sub == 0) rsq[r] = rsqrtf(s*(1.f/48.f) + 1e-6f);
    }
    __syncthreads();
    float* dst = g_xfeat + (size_t)(b*NQ+q0)*DX;
    for (int idx = t; idx < 16*DX; idx += 256){
        int r = idx/DX, d = idx - r*DX;
        float val;
        if (d < DF){
            int js = d/48, in = d - js*48;
            val = rows[r*768 + in*16 + c_comps[js]] * rsq[r] * lnw[in];
        } else val = (d == DF) ? 1.f : 0.f;
        dst[idx] = rnd_tf32(val);
    }
}

// ============ K2m: M[b,h][k][544] = Wq^T-folded kfeat + bias col ============
__global__ void __launch_bounds__(384) k2m_M(const float* __restrict__ bq){
    extern __shared__ float smm[];
    float* kf     = smm;                 // [i 48][k 256] pad 258
    float* ws     = smm + 48*258;        // [in 48][i 48]
    float* bias_s = ws + 2304;           // 256
    int h = blockIdx.x, b = blockIdx.y, t = threadIdx.x;
    int in = t % 48, kg = t / 48;        // kg 0..7 (32 keys each)
    size_t kbase = (size_t)((b*HH+h)*NK);

    for (int js = 0; js < 11; js++){
        int g = c_cg[js];
        __syncthreads();
        for (int idx = t; idx < 48*NK; idx += 384){
            int k = idx/48, i = idx - k*48;
            kf[i*258 + k] = g_kfeatT[(kbase + k)*DFP + js*48 + i];
        }
        for (int idx = t; idx < 2304; idx += 384){
            int inn = idx/48, i = idx - inn*48;
            ws[idx] = g_WqT[(g*48+inn)*384 + h*48 + i];
        }
        __syncthreads();
        if (js == 0 && t < NK){
            float s = g_kfeatT[(kbase + t)*DFP + 528];
            for (int i = 0; i < 48; i++) s += bq[h*48+i]*kf[i*258 + t];
            bias_s[t] = s;
        }
        u64 acc[16];
        #pragma unroll
        for (int p = 0; p < 16; p++) acc[p] = 0ull;
        #pragma unroll 4
        for (int i = 0; i < 48; i++){
            float w = ws[in*48 + i];
            u64 w2 = pk2(w, w);
            const float* kp = kf + i*258 + kg*32;
            #pragma unroll
            for (int p = 0; p < 16; p++)
                acc[p] = f2fma(*(const u64*)(kp + 2*p), w2, acc[p]);
        }
        __syncthreads();
        #pragma unroll
        for (int p = 0; p < 16; p++) *(u64*)&kf[in*258 + kg*32 + 2*p] = acc[p];
        __syncthreads();
        for (int idx = t; idx < 48*NK; idx += 384){
            int k = idx/48, i2 = idx - k*48;
            g_M[(kbase + k)*DX + js*48 + i2] = rnd_tf32(kf[i2*258 + k]);
        }
    }
    __syncthreads();
    for (int idx = t; idx < NK*16; idx += 384){
        int k = idx/16, cc = idx - k*16;
        float v = (cc == 0) ? bias_s[k] : 0.f;
        g_M[(kbase + k)*DX + DF + cc] = rnd_tf32(v);
    }
}

// ============ shared GEMM core: 64 rows x 256 cols, mma.sync tf32 ===========
// As: [64][36], Bs: [256][36]; values pre-rounded to tf32 -> raw bit loads
__device__ __forceinline__ void gemm_chunk(const float* As, const float* Bs,
                                           float acc[4][4][4], int wid, int lane){
    int g = lane >> 2, t4 = lane & 3;
    #pragma unroll
    for (int k8 = 0; k8 < 4; k8++){
        u32 au[4][4];
        #pragma unroll
        for (int mt = 0; mt < 4; mt++){
            const float* ap = As + (mt*16 + g)*36 + k8*8 + t4;
            au[mt][0] = __float_as_uint(ap[0]);
            au[mt][1] = __float_as_uint(ap[8*36]);
            au[mt][2] = __float_as_uint(ap[4]);
            au[mt][3] = __float_as_uint(ap[8*36+4]);
        }
        u32 bu[4][2];
        #pragma unroll
        for (int nt8 = 0; nt8 < 4; nt8++){
            const float* bp = Bs + (wid*32 + nt8*8 + g)*36 + k8*8 + t4;
            bu[nt8][0] = __float_as_uint(bp[0]);
            bu[nt8][1] = __float_as_uint(bp[4]);
        }
        #pragma unroll
        for (int mt = 0; mt < 4; mt++)
            #pragma unroll
            for (int nt8 = 0; nt8 < 4; nt8++)
                mma168(acc[mt][nt8], au[mt], bu[nt8]);
    }
}

// ===================== K2b: tf32 mma logits + softmax ======================
__global__ void __launch_bounds__(256) k2b_logits(){
    __shared__ float As[64*36];
    __shared__ float Bs[256*36];
    __shared__ float red[64*8];
    __shared__ float rmax[64];
    __shared__ float rsum[64];
    int t = threadIdx.x, wid = t>>5, lane = t&31;
    int g = lane>>2, t4 = lane&3;
    int qt = blockIdx.x, h = blockIdx.y, b = blockIdx.z;

    const float* Ag = g_xfeat + (size_t)(b*NQ + qt*64)*DX;
    const float* Bg = g_M     + (size_t)((b*HH+h)*NK)*DX;

    float acc[4][4][4];
    #pragma unroll
    for (int mt = 0; mt < 4; mt++)
        #pragma unroll
        for (int nt8 = 0; nt8 < 4; nt8++)
            #pragma unroll
            for (int r = 0; r < 4; r++) acc[mt][nt8][r] = 0.f;

    for (int kc = 0; kc < 17; kc++){
        #pragma unroll
        for (int it = 0; it < 2; it++){
            int i = t + 256*it;
            int row = i >> 3, kq = (i & 7)*4;
            float4 v = *(const float4*)(Ag + (size_t)row*DX + kc*32 + kq);
            *(float4*)&As[row*36 + kq] = v;
        }
        #pragma unroll
        for (int it = 0; it < 8; it++){
            int i = t + 256*it;
            int row = i >> 3, kq = (i & 7)*4;
            float4 v = *(const float4*)(Bg + (size_t)row*DX + kc*32 + kq);
            *(float4*)&Bs[row*36 + kq] = v;
        }
        __syncthreads();
        gemm_chunk(As, Bs, acc, wid, lane);
        __syncthreads();
    }

    // ---- softmax ----
    #pragma unroll
    for (int mt = 0; mt < 4; mt++)
        #pragma unroll
        for (int i = 0; i < 2; i++){
            float m = -1e30f;
            #pragma unroll
            for (int nt8 = 0; nt8 < 4; nt8++)
                m = fmaxf(m, fmaxf(acc[mt][nt8][2*i], acc[mt][nt8][2*i+1]));
            m = fmaxf(m, __shfl_xor_sync(~0u, m, 1));
            m = fmaxf(m, __shfl_xor_sync(~0u, m, 2));
            if (t4 == 0) red[(mt*16 + g + i*8)*8 + wid] = m;
        }
    __syncthreads();
    if (t < 64){
        float m = red[t*8];
        #pragma unroll
        for (int j = 1; j < 8; j++) m = fmaxf(m, red[t*8+j]);
        rmax[t] = m;
    }
    __syncthreads();
    #pragma unroll
    for (int mt = 0; mt < 4; mt++)
        #pragma unroll
        for (int i = 0; i < 2; i++){
            float mm = rmax[mt*16 + g + i*8];
            float s = 0.f;
            #pragma unroll
            for (int nt8 = 0; nt8 < 4; nt8++){
                float e0 = __expf(acc[mt][nt8][2*i]   - mm);
                float e1 = __expf(acc[mt][nt8][2*i+1] - mm);
                acc[mt][nt8][2*i] = e0; acc[mt][nt8][2*i+1] = e1;
                s += e0 + e1;
            }
            s += __shfl_xor_sync(~0u, s, 1);
            s += __shfl_xor_sync(~0u, s, 2);
            if (t4 == 0) red[(mt*16 + g + i*8)*8 + wid] = s;
        }
    __syncthreads();
    if (t < 64){
        float s = red[t*8];
        #pragma unroll
        for (int j = 1; j < 8; j++) s += red[t*8+j];
        rsum[t] = 1.f/s;
    }
    __syncthreads();
    #pragma unroll
    for (int mt = 0; mt < 4; mt++)
        #pragma unroll
        for (int i = 0; i < 2; i++){
            int row = mt*16 + g + i*8;
            float inv = rsum[row];
            float* dst = g_attn + (size_t)(b*NQ + qt*64 + row)*2048 + h*NK + wid*32;
            #pragma unroll
            for (int nt8 = 0; nt8 < 4; nt8++){
                float2 o = make_float2(rnd_tf32(acc[mt][nt8][2*i]*inv),
                                       rnd_tf32(acc[mt][nt8][2*i+1]*inv));
                *(float2*)(dst + nt8*8 + t4*2) = o;
            }
        }
}

// ===================== K3: tf32 mma attn @ vprojT + residual ================
__global__ void __launch_bounds__(256) k3_av(const float* __restrict__ hidden,
                                             const float* __restrict__ bo,
                                             float* __restrict__ out){
    __shared__ float As[64*36];
    __shared__ float Bs[256*36];
    int t = threadIdx.x, wid = t>>5, lane = t&31;
    int g = lane>>2, t4 = lane&3;
    int nt = blockIdx.x, qt = blockIdx.y, b = blockIdx.z;

    const float* Ag = g_attn   + (size_t)(b*NQ + qt*64)*2048;
    const float* Bg = g_vprojT + (size_t)(b*768 + nt*256)*2048;

    float acc[4][4][4];
    #pragma unroll
    for (int mt = 0; mt < 4; mt++)
        #pragma unroll
        for (int nt8 = 0; nt8 < 4; nt8++)
            #pragma unroll
            for (int r = 0; r < 4; r++) acc[mt][nt8][r] = 0.f;

    for (int kc = 0; kc < 64; kc++){
        #pragma unroll
        for (int it = 0; it < 2; it++){
            int i = t + 256*it;
            int row = i >> 3, kq = (i & 7)*4;
            float4 v = *(const float4*)(Ag + (size_t)row*2048 + kc*32 + kq);
            *(float4*)&As[row*36 + kq] = v;
        }
        #pragma unroll
        for (int it = 0; it < 8; it++){
            int i = t + 256*it;
            int row = i >> 3, kq = (i & 7)*4;
            float4 v = *(const float4*)(Bg + (size_t)row*2048 + kc*32 + kq);
            *(float4*)&Bs[row*36 + kq] = v;
        }
        __syncthreads();
        gemm_chunk(As, Bs, acc, wid, lane);
        __syncthreads();
    }

    #pragma unroll
    for (int mt = 0; mt < 4; mt++)
        #pragma unroll
        for (int i = 0; i < 2; i++){
            int row = qt*64 + mt*16 + g + i*8;
            const float* hb = hidden + (size_t)(b*NQ + row)*768;
            float*       ob = out    + (size_t)(b*NQ + row)*768;
            #pragma unroll
            for (int nt8 = 0; nt8 < 4; nt8++){
                int col = nt*256 + wid*32 + nt8*8 + t4*2;
                float2 hv = *(const float2*)(hb + col);
                float vx = acc[mt][nt8][2*i]   + hv.x;
                float vy = acc[mt][nt8][2*i+1] + hv.y;
                if ((col & 15) == 0) vx += bo[col >> 4];
                *(float2*)(ob + col) = make_float2(vx, vy);
            }
        }
}

// ===========================================================================
extern "C" void kernel_launch(void* const* d_in, const int* in_sizes, int n_in,
                              void* d_out, int out_size){
    const float* hidden = (const float*)d_in[0];
    const float* vision = (const float*)d_in[1];
    const float* lnw    = (const float*)d_in[2];
    const float* Wq     = (const float*)d_in[3];
    const float* bq     = (const float*)d_in[4];
    const float* Wkv    = (const float*)d_in[5];
    const float* bkv    = (const float*)d_in[6];
    const float* Wo     = (const float*)d_in[7];
    const float* bo     = (const float*)d_in[8];
    const float* daa    = (const float*)d_in[9];
    float* out = (float*)d_out;

    const int s1a = (768*18 + 128)*4;
    const int s1b = (11520 + 768*18)*4;
    const int s2x = (16*768 + 16)*4;
    const int s2m = (48*258 + 2304 + 256)*4;
    cudaFuncSetAttribute(k1a_kv,    cudaFuncAttributeMaxDynamicSharedMemorySize, s1a);
    cudaFuncSetAttribute(k1b_vproj, cudaFuncAttributeMaxDynamicSharedMemorySize, s1b);
    cudaFuncSetAttribute(k2x_xfeat, cudaFuncAttributeMaxDynamicSharedMemorySize, s2x);
    cudaFuncSetAttribute(k2m_M,     cudaFuncAttributeMaxDynamicSharedMemorySize, s2m);

    k0_prep   <<<128, 256>>>(Wq, Wkv, Wo, daa);
    k1a_kv    <<<dim3(NK/16, BB), 256, s1a>>>(vision, bkv);
    k1b_vproj <<<dim3(3, HH, BB), 256, s1b>>>();
    k2x_xfeat <<<dim3(NQ/16, BB), 256, s2x>>>(hidden, lnw);
    k2m_M     <<<dim3(HH, BB), 384, s2m>>>(bq);
    k2b_logits<<<dim3(NQ/64, HH, BB), 256>>>();
    k3_av     <<<dim3(3, NQ/64, BB), 256>>>(hidden, bo, out);
}

// round 8
// speedup vs baseline: 1.5790x; 1.5790x over previous
#include <cuda_runtime.h>
#include <math.h>
#include <stdint.h>

#define BB 8
#define NQ 1024
#define NK 256
#define HH 8
#define DF 528
#define DFP 576
#define DX 544

typedef unsigned long long u64;
typedef unsigned int u32;

__constant__ int c_cg[11]    = {0,1,1,1,2,2,2,3,3,3,3};
__constant__ int c_comps[11] = {0,2,3,4,8,9,10,14,11,12,13};
__constant__ int c_grade[16] = {0,1,1,1,1,2,2,2,2,2,2,3,3,3,3,4};

__device__ float g_WqT [5*48*384];
__device__ float g_WkvT[5*48*768];
__device__ float g_WoT [5*384*48];
__device__ float g_sp  [8];
__device__ float g_xfeat [(size_t)BB*NQ*DX];
__device__ float g_M     [(size_t)BB*HH*NK*DX];
__device__ float g_kfeatT[(size_t)BB*HH*NK*DFP];
__device__ float g_vtmp  [(size_t)BB*HH*48*16*NK];
__device__ float g_vprojT[(size_t)BB*768*2048];
__device__ float g_attn  [(size_t)BB*NQ*2048];

__device__ __forceinline__ u64 pk2(float lo, float hi){
    u64 u; asm("mov.b64 %0,{%1,%2};" : "=l"(u) : "f"(lo), "f"(hi)); return u;
}
__device__ __forceinline__ void upk2(u64 u, float& lo, float& hi){
    asm("mov.b64 {%0,%1},%2;" : "=f"(lo), "=f"(hi) : "l"(u));
}
__device__ __forceinline__ u64 f2fma(u64 a, u64 b, u64 c){
    u64 d; asm("fma.rn.f32x2 %0,%1,%2,%3;" : "=l"(d) : "l"(a), "l"(b), "l"(c)); return d;
}
__device__ __forceinline__ u32 cvt_tf32(float x){
    u32 r; asm("cvt.rna.tf32.f32 %0,%1;" : "=r"(r) : "f"(x)); return r;
}
__device__ __forceinline__ float rnd_tf32(float x){ return __uint_as_float(cvt_tf32(x)); }
__device__ __forceinline__ void mma168(float* d, const u32* a, const u32* b){
    asm volatile("mma.sync.aligned.m16n8k8.row.col.f32.tf32.tf32.f32 "
        "{%0,%1,%2,%3},{%4,%5,%6,%7},{%8,%9},{%0,%1,%2,%3};"
        : "+f"(d[0]), "+f"(d[1]), "+f"(d[2]), "+f"(d[3])
        : "r"(a[0]), "r"(a[1]), "r"(a[2]), "r"(a[3]), "r"(b[0]), "r"(b[1]));
}

// ===================== K0: weight transposes + softplus =====================
__global__ void k0_prep(const float* __restrict__ Wq, const float* __restrict__ Wkv,
                        const float* __restrict__ Wo, const float* __restrict__ daa){
    int stride = gridDim.x * blockDim.x;
    int gid = blockIdx.x * blockDim.x + threadIdx.x;
    for (int idx = gid; idx < 5*384*48; idx += stride){
        int g = idx/(384*48), rem = idx%(384*48), o = rem/48, i = rem%48;
        g_WqT[(g*48+i)*384+o] = Wq[idx];
    }
    for (int idx = gid; idx < 5*768*48; idx += stride){
        int g = idx/(768*48), rem = idx%(768*48), o = rem/48, i = rem%48;
        g_WkvT[(g*48+i)*768+o] = Wkv[idx];
    }
    for (int idx = gid; idx < 5*48*384; idx += stride){
        int g = idx/(48*384), rem = idx%(48*384), o = rem/384, i = rem%384;
        g_WoT[(g*384+i)*48+o] = Wo[idx];
    }
    if (gid < 8){
        float x = daa[gid];
        g_sp[gid] = (x > 20.f) ? x : log1pf(expf(x));
    }
}

// ========== K1a: kv projection, 16 keys/block -> kfeatT(row-major)/vtmp =====
__global__ void __launch_bounds__(256) k1a_kv(const float* __restrict__ vision,
                                              const float* __restrict__ bkv){
    extern __shared__ float sm1[];
    float* xT  = sm1;           // [(c*48+in)][key16] pad 18
    float* k2s = sm1 + 768*18;  // [h*16+key]
    int b = blockIdx.y, k0 = blockIdx.x*16, t = threadIdx.x;

    for (int idx = t; idx < 16*768; idx += 256){
        int key = idx/768, e = idx - key*768, in = e>>4, c = e&15;
        xT[(c*48+in)*18 + key] = vision[((size_t)(b*NK + k0 + key))*768 + e];
    }
    if (t < 128) k2s[t] = 0.f;
    __syncthreads();

    const float INVS = 0.051031036307982884f;  // 1/sqrt(384)
    const int GR[16] = {0,1,1,1,1,2,2,2,2,2,2,3,3,3,3,4};

    for (int s = 0; s < 3; s++){
        int o = t + 256*s;
        float bias = bkv[o];
        const float* wb = g_WkvT + o;
        for (int kt = 0; kt < 4; kt++){
            u64 acc[2][16];
            #pragma unroll
            for (int kp = 0; kp < 2; kp++){
                acc[kp][0] = pk2(bias, bias);
                #pragma unroll
                for (int c = 1; c < 16; c++) acc[kp][c] = 0ull;
            }
            #pragma unroll 4
            for (int in = 0; in < 48; in++){
                float w0 = wb[(0*48+in)*768], w1 = wb[(1*48+in)*768];
                float w2 = wb[(2*48+in)*768], w3 = wb[(3*48+in)*768];
                float w4 = wb[(4*48+in)*768];
                u64 wv[5] = {pk2(w0,w0), pk2(w1,w1), pk2(w2,w2), pk2(w3,w3), pk2(w4,w4)};
                #pragma unroll
                for (int c = 0; c < 16; c++){
                    const float* xp = xT + (c*48+in)*18 + kt*4;
                    acc[0][c] = f2fma(*(const u64*)(xp    ), wv[GR[c]], acc[0][c]);
                    acc[1][c] = f2fma(*(const u64*)(xp + 2), wv[GR[c]], acc[1][c]);
                }
            }
            if (o < 384){
                int h = o/48, i = o - h*48;
                float sp = g_sp[h], spc = sp*(2.f/48.f);
                size_t rb = (size_t)((b*HH+h)*NK + k0 + kt*4)*DFP;
                const int IC[8] = {0,2,3,4,8,9,10,14};
                #pragma unroll
                for (int js = 0; js < 8; js++)
                    #pragma unroll
                    for (int kp = 0; kp < 2; kp++){
                        float lo, hi; upk2(acc[kp][IC[js]], lo, hi);
                        g_kfeatT[rb + (size_t)(2*kp  )*DFP + js*48+i] = lo*INVS;
                        g_kfeatT[rb + (size_t)(2*kp+1)*DFP + js*48+i] = hi*INVS;
                    }
                const int PC[3] = {11,12,13};
                float s2[4] = {0.f,0.f,0.f,0.f};
                #pragma unroll
                for (int jp = 0; jp < 3; jp++)
                    #pragma unroll
                    for (int kp = 0; kp < 2; kp++){
                        float lo, hi; upk2(acc[kp][PC[jp]], lo, hi);
                        g_kfeatT[rb + (size_t)(2*kp  )*DFP + 384+jp*48+i] = lo*spc;
                        g_kfeatT[rb + (size_t)(2*kp+1)*DFP + 384+jp*48+i] = hi*spc;
                        s2[2*kp] += lo*lo; s2[2*kp+1] += hi*hi;
                    }
                #pragma unroll
                for (int kk = 0; kk < 4; kk++) atomicAdd(&k2s[h*16 + kt*4 + kk], s2[kk]);
            } else {
                int vc = o - 384, h = vc/48, i = vc - h*48;
                float* vb = g_vtmp + (size_t)(((b*HH+h)*48+i)*16)*NK + (k0 + kt*4);
                #pragma unroll
                for (int c = 0; c < 16; c++){
                    *(u64*)&vb[(size_t)c*NK]     = acc[0][c];
                    *(u64*)&vb[(size_t)c*NK + 2] = acc[1][c];
                }
            }
        }
    }
    __syncthreads();
    if (t < 128){
        int h = t>>4, key = t&15;
        g_kfeatT[(size_t)((b*HH+h)*NK + k0 + key)*DFP + 528] = -g_sp[h]*k2s[t]*(1.f/48.f);
    }
}

// ========== K1b: vprojT[b][col768][kh2048] (tf32 pre-rounded) ==============
__global__ void __launch_bounds__(256) k1b_vproj(){
    extern __shared__ float sm2[];
    float* w_s = sm2;            // [g][i*48+o48] 5*2304
    float* v_s = sm2 + 11520;    // [(i*16+c)][key16] pad 18
    int sl = blockIdx.x, h = blockIdx.y, b = blockIdx.z, t = threadIdx.x;

    for (int idx = t; idx < 11520; idx += 256){
        int g = idx/2304, r = idx - g*2304;
        w_s[idx] = g_WoT[(g*384 + h*48)*48 + r];
    }
    int j = sl*256 + t;
    int o48 = j>>4, c = j&15, g = c_grade[c];
    const size_t vbase = (size_t)((b*HH+h)*48)*16*NK;

    for (int kt = 0; kt < 16; kt++){
        __syncthreads();
        for (int idx = t; idx < 12288; idx += 256){
            int key = idx&15, rr = idx>>4;
            v_s[rr*18 + key] = g_vtmp[vbase + (size_t)rr*NK + kt*16 + key];
        }
        __syncthreads();
        u64 acc[8];
        #pragma unroll
        for (int kp = 0; kp < 8; kp++) acc[kp] = 0ull;
        #pragma unroll 4
        for (int i = 0; i < 48; i++){
            float ww = w_s[g*2304 + i*48 + o48];
            u64 w2 = pk2(ww, ww);
            const float* vp = v_s + (i*16+c)*18;
            #pragma unroll
            for (int kp = 0; kp < 8; kp++)
                acc[kp] = f2fma(*(const u64*)(vp + 2*kp), w2, acc[kp]);
        }
        float* dst = g_vprojT + (size_t)(b*768 + j)*2048 + h*NK + kt*16;
        #pragma unroll
        for (int kp = 0; kp < 8; kp++){
            float lo, hi; upk2(acc[kp], lo, hi);
            dst[2*kp]   = rnd_tf32(lo);
            dst[2*kp+1] = rnd_tf32(hi);
        }
    }
}

// ============ K2x: rmsnorm + reorder -> xfeat [row][544] (tf32) =============
__global__ void __launch_bounds__(256) k2x_xfeat(const float* __restrict__ hidden,
                                                 const float* __restrict__ lnw){
    extern __shared__ float sx[];
    float* rows = sx;               // 16*768
    float* rsq  = sx + 16*768;      // 16
    int b = blockIdx.y, q0 = blockIdx.x*16, t = threadIdx.x;
    const float* hrow = hidden + (size_t)(b*NQ+q0)*768;
    for (int idx = t; idx < 16*768; idx += 256) rows[idx] = hrow[idx];
    __syncthreads();
    { int r = t>>4, sub = t&15; float s = 0.f;
      for (int e = sub; e < 768; e += 16){ float v = rows[r*768+e]; s += v*v; }
      s += __shfl_xor_sync(~0u, s, 1);
      s += __shfl_xor_sync(~0u, s, 2);
      s += __shfl_xor_sync(~0u, s, 4);
      s += __shfl_xor_sync(~0u, s, 8);
      if (sub == 0) rsq[r] = rsqrtf(s*(1.f/48.f) + 1e-6f);
    }
    __syncthreads();
    float* dst = g_xfeat + (size_t)(b*NQ+q0)*DX;
    for (int idx = t; idx < 16*DX; idx += 256){
        int r = idx/DX, d = idx - r*DX;
        float val;
        if (d < DF){
            int js = d/48, in = d - js*48;
            val = rows[r*768 + in*16 + c_comps[js]] * rsq[r] * lnw[in];
        } else val = (d == DF) ? 1.f : 0.f;
        dst[idx] = rnd_tf32(val);
    }
}

// ======= K2m v2: M[b,h][k][544] — 512 CTAs, 32 keys each ====================
// M[k][js*48+c] = sum_j Wq[g][h*48+j][c] * kfeat[k][js*48+j]
__global__ void __launch_bounds__(256) k2m_M(const float* __restrict__ bq){
    __shared__ float kfT[48*34];   // [j][key32] pad 34
    __shared__ float ws [48*49];   // [j][c] pad 49
    __shared__ float mT [48*34];   // [c][key32] pad 34
    __shared__ float kb32[32];
    int kt0 = blockIdx.x*32, h = blockIdx.y, b = blockIdx.z, t = threadIdx.x;
    size_t kbase = (size_t)((b*HH+h)*NK) + kt0;

    for (int js = 0; js < 11; js++){
        int g = c_cg[js];
        __syncthreads();
        #pragma unroll
        for (int r = 0; r < 6; r++){
            int idx = t + 256*r;                // 48*32 = 1536
            if (idx < 1536){
                int k = idx/48, j = idx - k*48;
                kfT[j*34 + k] = g_kfeatT[(kbase + k)*DFP + js*48 + j];
            }
        }
        #pragma unroll
        for (int r = 0; r < 9; r++){
            int idx = t + 256*r;                // 2304
            if (idx < 2304){
                int c = idx/48, j = idx - c*48;
                ws[j*49 + c] = g_WqT[(g*48+c)*384 + h*48 + j];
            }
        }
        __syncthreads();
        if (js == 0 && t < 32){
            float s = g_kfeatT[(kbase + t)*DFP + 528];
            #pragma unroll 8
            for (int j = 0; j < 48; j++) s += bq[h*48+j]*kfT[j*34 + t];
            kb32[t] = s;
        }
        #pragma unroll
        for (int r = 0; r < 3; r++){
            int o = t + 256*r;                  // 768 = 48c * 16 keypairs
            int c = o >> 4, kp = o & 15;
            u64 acc = 0ull;
            #pragma unroll 8
            for (int j = 0; j < 48; j++){
                float w = ws[j*49 + c];
                acc = f2fma(*(const u64*)&kfT[j*34 + 2*kp], pk2(w, w), acc);
            }
            *(u64*)&mT[c*34 + 2*kp] = acc;
        }
        __syncthreads();
        #pragma unroll
        for (int r = 0; r < 6; r++){
            int idx = t + 256*r;
            if (idx < 1536){
                int k = idx/48, c = idx - k*48;
                g_M[(kbase + k)*DX + js*48 + c] = rnd_tf32(mT[c*34 + k]);
            }
        }
    }
    __syncthreads();
    #pragma unroll
    for (int r = 0; r < 2; r++){
        int idx = t + 256*r;                    // 32*16 = 512
        int k = idx >> 4, cc = idx & 15;
        g_M[(kbase + k)*DX + DF + cc] = (cc == 0) ? rnd_tf32(kb32[k]) : 0.f;
    }
}

// ============ shared GEMM core: 64 rows x 256 cols, mma.sync tf32 ===========
__device__ __forceinline__ void gemm_chunk(const float* As, const float* Bs,
                                           float acc[4][4][4], int wid, int lane){
    int g = lane >> 2, t4 = lane & 3;
    #pragma unroll
    for (int k8 = 0; k8 < 4; k8++){
        u32 au[4][4];
        #pragma unroll
        for (int mt = 0; mt < 4; mt++){
            const float* ap = As + (mt*16 + g)*36 + k8*8 + t4;
            au[mt][0] = __float_as_uint(ap[0]);
            au[mt][1] = __float_as_uint(ap[8*36]);
            au[mt][2] = __float_as_uint(ap[4]);
            au[mt][3] = __float_as_uint(ap[8*36+4]);
        }
        u32 bu[4][2];
        #pragma unroll
        for (int nt8 = 0; nt8 < 4; nt8++){
            const float* bp = Bs + (wid*32 + nt8*8 + g)*36 + k8*8 + t4;
            bu[nt8][0] = __float_as_uint(bp[0]);
            bu[nt8][1] = __float_as_uint(bp[4]);
        }
        #pragma unroll
        for (int mt = 0; mt < 4; mt++)
            #pragma unroll
            for (int nt8 = 0; nt8 < 4; nt8++)
                mma168(acc[mt][nt8], au[mt], bu[nt8]);
    }
}

// ===================== K2b: tf32 mma logits + softmax ======================
__global__ void __launch_bounds__(256) k2b_logits(){
    __shared__ float As[64*36];
    __shared__ float Bs[256*36];
    __shared__ float red[64*8];
    __shared__ float rmax[64];
    __shared__ float rsum[64];
    int t = threadIdx.x, wid = t>>5, lane = t&31;
    int g = lane>>2, t4 = lane&3;
    int qt = blockIdx.x, h = blockIdx.y, b = blockIdx.z;

    const float* Ag = g_xfeat + (size_t)(b*NQ + qt*64)*DX;
    const float* Bg = g_M     + (size_t)((b*HH+h)*NK)*DX;

    float acc[4][4][4];
    #pragma unroll
    for (int mt = 0; mt < 4; mt++)
        #pragma unroll
        for (int nt8 = 0; nt8 < 4; nt8++)
            #pragma unroll
            for (int r = 0; r < 4; r++) acc[mt][nt8][r] = 0.f;

    for (int kc = 0; kc < 17; kc++){
        #pragma unroll
        for (int it = 0; it < 2; it++){
            int i = t + 256*it;
            int row = i >> 3, kq = (i & 7)*4;
            float4 v = *(const float4*)(Ag + (size_t)row*DX + kc*32 + kq);
            *(float4*)&As[row*36 + kq] = v;
        }
        #pragma unroll
        for (int it = 0; it < 8; it++){
            int i = t + 256*it;
            int row = i >> 3, kq = (i & 7)*4;
            float4 v = *(const float4*)(Bg + (size_t)row*DX + kc*32 + kq);
            *(float4*)&Bs[row*36 + kq] = v;
        }
        __syncthreads();
        gemm_chunk(As, Bs, acc, wid, lane);
        __syncthreads();
    }

    // ---- softmax ----
    #pragma unroll
    for (int mt = 0; mt < 4; mt++)
        #pragma unroll
        for (int i = 0; i < 2; i++){
            float m = -1e30f;
            #pragma unroll
            for (int nt8 = 0; nt8 < 4; nt8++)
                m = fmaxf(m, fmaxf(acc[mt][nt8][2*i], acc[mt][nt8][2*i+1]));
            m = fmaxf(m, __shfl_xor_sync(~0u, m, 1));
            m = fmaxf(m, __shfl_xor_sync(~0u, m, 2));
            if (t4 == 0) red[(mt*16 + g + i*8)*8 + wid] = m;
        }
    __syncthreads();
    if (t < 64){
        float m = red[t*8];
        #pragma unroll
        for (int j = 1; j < 8; j++) m = fmaxf(m, red[t*8+j]);
        rmax[t] = m;
    }
    __syncthreads();
    #pragma unroll
    for (int mt = 0; mt < 4; mt++)
        #pragma unroll
        for (int i = 0; i < 2; i++){
            float mm = rmax[mt*16 + g + i*8];
            float s = 0.f;
            #pragma unroll
            for (int nt8 = 0; nt8 < 4; nt8++){
                float e0 = __expf(acc[mt][nt8][2*i]   - mm);
                float e1 = __expf(acc[mt][nt8][2*i+1] - mm);
                acc[mt][nt8][2*i] = e0; acc[mt][nt8][2*i+1] = e1;
                s += e0 + e1;
            }
            s += __shfl_xor_sync(~0u, s, 1);
            s += __shfl_xor_sync(~0u, s, 2);
            if (t4 == 0) red[(mt*16 + g + i*8)*8 + wid] = s;
        }
    __syncthreads();
    if (t < 64){
        float s = red[t*8];
        #pragma unroll
        for (int j = 1; j < 8; j++) s += red[t*8+j];
        rsum[t] = 1.f/s;
    }
    __syncthreads();
    #pragma unroll
    for (int mt = 0; mt < 4; mt++)
        #pragma unroll
        for (int i = 0; i < 2; i++){
            int row = mt*16 + g + i*8;
            float inv = rsum[row];
            float* dst = g_attn + (size_t)(b*NQ + qt*64 + row)*2048 + h*NK + wid*32;
            #pragma unroll
            for (int nt8 = 0; nt8 < 4; nt8++){
                float2 o = make_float2(rnd_tf32(acc[mt][nt8][2*i]*inv),
                                       rnd_tf32(acc[mt][nt8][2*i+1]*inv));
                *(float2*)(dst + nt8*8 + t4*2) = o;
            }
        }
}

// ===================== K3: tf32 mma attn @ vprojT + residual ================
__global__ void __launch_bounds__(256) k3_av(const float* __restrict__ hidden,
                                             const float* __restrict__ bo,
                                             float* __restrict__ out){
    __shared__ float As[64*36];
    __shared__ float Bs[256*36];
    int t = threadIdx.x, wid = t>>5, lane = t&31;
    int g = lane>>2, t4 = lane&3;
    int nt = blockIdx.x, qt = blockIdx.y, b = blockIdx.z;

    const float* Ag = g_attn   + (size_t)(b*NQ + qt*64)*2048;
    const float* Bg = g_vprojT + (size_t)(b*768 + nt*256)*2048;

    float acc[4][4][4];
    #pragma unroll
    for (int mt = 0; mt < 4; mt++)
        #pragma unroll
        for (int nt8 = 0; nt8 < 4; nt8++)
            #pragma unroll
            for (int r = 0; r < 4; r++) acc[mt][nt8][r] = 0.f;

    for (int kc = 0; kc < 64; kc++){
        #pragma unroll
        for (int it = 0; it < 2; it++){
            int i = t + 256*it;
            int row = i >> 3, kq = (i & 7)*4;
            float4 v = *(const float4*)(Ag + (size_t)row*2048 + kc*32 + kq);
            *(float4*)&As[row*36 + kq] = v;
        }
        #pragma unroll
        for (int it = 0; it < 8; it++){
            int i = t + 256*it;
            int row = i >> 3, kq = (i & 7)*4;
            float4 v = *(const float4*)(Bg + (size_t)row*2048 + kc*32 + kq);
            *(float4*)&Bs[row*36 + kq] = v;
        }
        __syncthreads();
        gemm_chunk(As, Bs, acc, wid, lane);
        __syncthreads();
    }

    #pragma unroll
    for (int mt = 0; mt < 4; mt++)
        #pragma unroll
        for (int i = 0; i < 2; i++){
            int row = qt*64 + mt*16 + g + i*8;
            const float* hb = hidden + (size_t)(b*NQ + row)*768;
            float*       ob = out    + (size_t)(b*NQ + row)*768;
            #pragma unroll
            for (int nt8 = 0; nt8 < 4; nt8++){
                int col = nt*256 + wid*32 + nt8*8 + t4*2;
                float2 hv = *(const float2*)(hb + col);
                float vx = acc[mt][nt8][2*i]   + hv.x;
                float vy = acc[mt][nt8][2*i+1] + hv.y;
                if ((col & 15) == 0) vx += bo[col >> 4];
                *(float2*)(ob + col) = make_float2(vx, vy);
            }
        }
}

// ===========================================================================
extern "C" void kernel_launch(void* const* d_in, const int* in_sizes, int n_in,
                              void* d_out, int out_size){
    const float* hidden = (const float*)d_in[0];
    const float* vision = (const float*)d_in[1];
    const float* lnw    = (const float*)d_in[2];
    const float* Wq     = (const float*)d_in[3];
    const float* bq     = (const float*)d_in[4];
    const float* Wkv    = (const float*)d_in[5];
    const float* bkv    = (const float*)d_in[6];
    const float* Wo     = (const float*)d_in[7];
    const float* bo     = (const float*)d_in[8];
    const float* daa    = (const float*)d_in[9];
    float* out = (float*)d_out;

    const int s1a = (768*18 + 128)*4;
    const int s1b = (11520 + 768*18)*4;
    const int s2x = (16*768 + 16)*4;
    cudaFuncSetAttribute(k1a_kv,    cudaFuncAttributeMaxDynamicSharedMemorySize, s1a);
    cudaFuncSetAttribute(k1b_vproj, cudaFuncAttributeMaxDynamicSharedMemorySize, s1b);
    cudaFuncSetAttribute(k2x_xfeat, cudaFuncAttributeMaxDynamicSharedMemorySize, s2x);

    k0_prep   <<<128, 256>>>(Wq, Wkv, Wo, daa);
    k1a_kv    <<<dim3(NK/16, BB), 256, s1a>>>(vision, bkv);
    k1b_vproj <<<dim3(3, HH, BB), 256, s1b>>>();
    k2x_xfeat <<<dim3(NQ/16, BB), 256, s2x>>>(hidden, lnw);
    k2m_M     <<<dim3(NK/32, HH, BB), 256>>>(bq);
    k2b_logits<<<dim3(NQ/64, HH, BB), 256>>>();
    k3_av     <<<dim3(3, NQ/64, BB), 256>>>(hidden, bo, out);
}

// round 9
// speedup vs baseline: 1.7706x; 1.1214x over previous
#include <cuda_runtime.h>
#include <math.h>
#include <stdint.h>

#define BB 8
#define NQ 1024
#define NK 256
#define HH 8
#define DF 528
#define DFP 576
#define DX 544

typedef unsigned long long u64;
typedef unsigned int u32;

__constant__ int c_cg[11]    = {0,1,1,1,2,2,2,3,3,3,3};
__constant__ int c_comps[11] = {0,2,3,4,8,9,10,14,11,12,13};
__constant__ int c_grade[16] = {0,1,1,1,1,2,2,2,2,2,2,3,3,3,3,4};

__device__ float g_WqT [5*48*384];
__device__ float g_WkvT[5*48*768];
__device__ float g_WoT [5*384*48];
__device__ float g_sp  [8];
__device__ float g_xfeat [(size_t)BB*NQ*DX];
__device__ float g_M     [(size_t)BB*HH*NK*DX];
__device__ float g_kfeatT[(size_t)BB*HH*NK*DFP];
__device__ float g_vtmp  [(size_t)BB*HH*48*16*NK];
__device__ float g_vprojT[(size_t)BB*768*2048];
__device__ float g_attn  [(size_t)BB*NQ*2048];

__device__ __forceinline__ u64 pk2(float lo, float hi){
    u64 u; asm("mov.b64 %0,{%1,%2};" : "=l"(u) : "f"(lo), "f"(hi)); return u;
}
__device__ __forceinline__ void upk2(u64 u, float& lo, float& hi){
    asm("mov.b64 {%0,%1},%2;" : "=f"(lo), "=f"(hi) : "l"(u));
}
__device__ __forceinline__ u64 f2fma(u64 a, u64 b, u64 c){
    u64 d; asm("fma.rn.f32x2 %0,%1,%2,%3;" : "=l"(d) : "l"(a), "l"(b), "l"(c)); return d;
}
__device__ __forceinline__ u32 cvt_tf32(float x){
    u32 r; asm("cvt.rna.tf32.f32 %0,%1;" : "=r"(r) : "f"(x)); return r;
}
__device__ __forceinline__ float rnd_tf32(float x){ return __uint_as_float(cvt_tf32(x)); }
__device__ __forceinline__ u32 smem_u32(const void* p){
    u32 a; asm("{ .reg .u64 t; cvta.to.shared.u64 t, %1; cvt.u32.u64 %0, t; }" : "=r"(a) : "l"(p));
    return a;
}
__device__ __forceinline__ void mma168(float* d, const u32* a, const u32* b){
    asm volatile("mma.sync.aligned.m16n8k8.row.col.f32.tf32.tf32.f32 "
        "{%0,%1,%2,%3},{%4,%5,%6,%7},{%8,%9},{%0,%1,%2,%3};"
        : "+f"(d[0]), "+f"(d[1]), "+f"(d[2]), "+f"(d[3])
        : "r"(a[0]), "r"(a[1]), "r"(a[2]), "r"(a[3]), "r"(b[0]), "r"(b[1]));
}
__device__ __forceinline__ void cp16(u32 sdst, const float* gsrc){
    asm volatile("cp.async.cg.shared.global [%0], [%1], 16;" :: "r"(sdst), "l"(gsrc));
}

// ===================== K0: weight transposes + softplus =====================
__global__ void k0_prep(const float* __restrict__ Wq, const float* __restrict__ Wkv,
                        const float* __restrict__ Wo, const float* __restrict__ daa){
    int stride = gridDim.x * blockDim.x;
    int gid = blockIdx.x * blockDim.x + threadIdx.x;
    for (int idx = gid; idx < 5*384*48; idx += stride){
        int g = idx/(384*48), rem = idx%(384*48), o = rem/48, i = rem%48;
        g_WqT[(g*48+i)*384+o] = Wq[idx];
    }
    for (int idx = gid; idx < 5*768*48; idx += stride){
        int g = idx/(768*48), rem = idx%(768*48), o = rem/48, i = rem%48;
        g_WkvT[(g*48+i)*768+o] = Wkv[idx];
    }
    for (int idx = gid; idx < 5*48*384; idx += stride){
        int g = idx/(48*384), rem = idx%(48*384), o = rem/384, i = rem%384;
        g_WoT[(g*384+i)*48+o] = Wo[idx];
    }
    if (gid < 8){
        float x = daa[gid];
        g_sp[gid] = (x > 20.f) ? x : log1pf(expf(x));
    }
}

// ========== K1a: kv projection; grid (ktile, s, b) -> kfeatT/vtmp ===========
__global__ void __launch_bounds__(256) k1a_kv(const float* __restrict__ vision,
                                              const float* __restrict__ bkv){
    extern __shared__ float sm1[];
    float* xT = sm1;            // [(c*48+in)][key16] pad 18
    int b = blockIdx.z, s = blockIdx.y, k0 = blockIdx.x*16, t = threadIdx.x;

    for (int idx = t; idx < 16*768; idx += 256){
        int key = idx/768, e = idx - key*768, in = e>>4, c = e&15;
        xT[(c*48+in)*18 + key] = vision[((size_t)(b*NK + k0 + key))*768 + e];
    }
    __syncthreads();

    const float INVS = 0.051031036307982884f;  // 1/sqrt(384)
    const int GR[16] = {0,1,1,1,1,2,2,2,2,2,2,3,3,3,3,4};

    int o = t + 256*s;
    float bias = bkv[o];
    const float* wb = g_WkvT + o;
    for (int kt = 0; kt < 4; kt++){
        u64 acc[2][16];
        #pragma unroll
        for (int kp = 0; kp < 2; kp++){
            acc[kp][0] = pk2(bias, bias);
            #pragma unroll
            for (int c = 1; c < 16; c++) acc[kp][c] = 0ull;
        }
        #pragma unroll 4
        for (int in = 0; in < 48; in++){
            float w0 = wb[(0*48+in)*768], w1 = wb[(1*48+in)*768];
            float w2 = wb[(2*48+in)*768], w3 = wb[(3*48+in)*768];
            float w4 = wb[(4*48+in)*768];
            u64 wv[5] = {pk2(w0,w0), pk2(w1,w1), pk2(w2,w2), pk2(w3,w3), pk2(w4,w4)};
            #pragma unroll
            for (int c = 0; c < 16; c++){
                const float* xp = xT + (c*48+in)*18 + kt*4;
                acc[0][c] = f2fma(*(const u64*)(xp    ), wv[GR[c]], acc[0][c]);
                acc[1][c] = f2fma(*(const u64*)(xp + 2), wv[GR[c]], acc[1][c]);
            }
        }
        if (o < 384){
            int h = o/48, i = o - h*48;
            float sp = g_sp[h], spc = sp*(2.f/48.f);
            size_t rb = (size_t)((b*HH+h)*NK + k0 + kt*4)*DFP;
            const int IC[8] = {0,2,3,4,8,9,10,14};
            #pragma unroll
            for (int js = 0; js < 8; js++)
                #pragma unroll
                for (int kp = 0; kp < 2; kp++){
                    float lo, hi; upk2(acc[kp][IC[js]], lo, hi);
                    g_kfeatT[rb + (size_t)(2*kp  )*DFP + js*48+i] = lo*INVS;
                    g_kfeatT[rb + (size_t)(2*kp+1)*DFP + js*48+i] = hi*INVS;
                }
            const int PC[3] = {11,12,13};
            #pragma unroll
            for (int jp = 0; jp < 3; jp++)
                #pragma unroll
                for (int kp = 0; kp < 2; kp++){
                    float lo, hi; upk2(acc[kp][PC[jp]], lo, hi);
                    g_kfeatT[rb + (size_t)(2*kp  )*DFP + 384+jp*48+i] = lo*spc;
                    g_kfeatT[rb + (size_t)(2*kp+1)*DFP + 384+jp*48+i] = hi*spc;
                }
        } else {
            int vc = o - 384, h = vc/48, i = vc - h*48;
            float* vb = g_vtmp + (size_t)(((b*HH+h)*48+i)*16)*NK + (k0 + kt*4);
            #pragma unroll
            for (int c = 0; c < 16; c++){
                *(u64*)&vb[(size_t)c*NK]     = acc[0][c];
                *(u64*)&vb[(size_t)c*NK + 2] = acc[1][c];
            }
        }
    }
}

// ========== K1b: vprojT[b][col768][kh2048] (tf32 pre-rounded) ==============
__global__ void __launch_bounds__(256) k1b_vproj(){
    extern __shared__ float sm2[];
    float* w_s = sm2;            // [g][i*48+o48] 5*2304
    float* v_s = sm2 + 11520;    // [(i*16+c)][key16] pad 18
    int sl = blockIdx.x, h = blockIdx.y, b = blockIdx.z, t = threadIdx.x;

    for (int idx = t; idx < 11520; idx += 256){
        int g = idx/2304, r = idx - g*2304;
        w_s[idx] = g_WoT[(g*384 + h*48)*48 + r];
    }
    int j = sl*256 + t;
    int o48 = j>>4, c = j&15, g = c_grade[c];
    const size_t vbase = (size_t)((b*HH+h)*48)*16*NK;

    for (int kt = 0; kt < 16; kt++){
        __syncthreads();
        for (int idx = t; idx < 12288; idx += 256){
            int key = idx&15, rr = idx>>4;
            v_s[rr*18 + key] = g_vtmp[vbase + (size_t)rr*NK + kt*16 + key];
        }
        __syncthreads();
        u64 acc[8];
        #pragma unroll
        for (int kp = 0; kp < 8; kp++) acc[kp] = 0ull;
        #pragma unroll 4
        for (int i = 0; i < 48; i++){
            float ww = w_s[g*2304 + i*48 + o48];
            u64 w2 = pk2(ww, ww);
            const float* vp = v_s + (i*16+c)*18;
            #pragma unroll
            for (int kp = 0; kp < 8; kp++)
                acc[kp] = f2fma(*(const u64*)(vp + 2*kp), w2, acc[kp]);
        }
        float* dst = g_vprojT + (size_t)(b*768 + j)*2048 + h*NK + kt*16;
        #pragma unroll
        for (int kp = 0; kp < 8; kp++){
            float lo, hi; upk2(acc[kp], lo, hi);
            dst[2*kp]   = rnd_tf32(lo);
            dst[2*kp+1] = rnd_tf32(hi);
        }
    }
}

// ============ K2x: rmsnorm + reorder -> xfeat [row][544] (tf32) =============
__global__ void __launch_bounds__(256) k2x_xfeat(const float* __restrict__ hidden,
                                                 const float* __restrict__ lnw){
    extern __shared__ float sx[];
    float* rows = sx;               // 16*768
    float* rsq  = sx + 16*768;      // 16
    int b = blockIdx.y, q0 = blockIdx.x*16, t = threadIdx.x;
    const float* hrow = hidden + (size_t)(b*NQ+q0)*768;
    for (int idx = t; idx < 16*768; idx += 256) rows[idx] = hrow[idx];
    __syncthreads();
    { int r = t>>4, sub = t&15; float s = 0.f;
      for (int e = sub; e < 768; e += 16){ float v = rows[r*768+e]; s += v*v; }
      s += __shfl_xor_sync(~0u, s, 1);
      s += __shfl_xor_sync(~0u, s, 2);
      s += __shfl_xor_sync(~0u, s, 4);
      s += __shfl_xor_sync(~0u, s, 8);
      if (sub == 0) rsq[r] = rsqrtf(s*(1.f/48.f) + 1e-6f);
    }
    __syncthreads();
    float* dst = g_xfeat + (size_t)(b*NQ+q0)*DX;
    for (int idx = t; idx < 16*DX; idx += 256){
        int r = idx/DX, d = idx - r*DX;
        float val;
        if (d < DF){
            int js = d/48, in = d - js*48;
            val = rows[r*768 + in*16 + c_comps[js]] * rsq[r] * lnw[in];
        } else val = (d == DF) ? 1.f : 0.f;
        dst[idx] = rnd_tf32(val);
    }
}

// ======= K2m: M[b,h][k][544] — 512 CTAs, 32 keys each; bias col built here ==
__global__ void __launch_bounds__(256) k2m_M(const float* __restrict__ bq){
    __shared__ float kfT[48*34];   // [j][key32] pad 34
    __shared__ float ws [48*49];   // [j][c] pad 49
    __shared__ float mT [48*34];   // [c][key32] pad 34
    __shared__ float kb32[32];
    __shared__ float ss32[32];
    int kt0 = blockIdx.x*32, h = blockIdx.y, b = blockIdx.z, t = threadIdx.x;
    size_t kbase = (size_t)((b*HH+h)*NK) + kt0;
    if (t < 32) ss32[t] = 0.f;

    for (int js = 0; js < 11; js++){
        int g = c_cg[js];
        __syncthreads();
        #pragma unroll
        for (int r = 0; r < 6; r++){
            int idx = t + 256*r;                // 48*32 = 1536
            if (idx < 1536){
                int k = idx/48, j = idx - k*48;
                kfT[j*34 + k] = g_kfeatT[(kbase + k)*DFP + js*48 + j];
            }
        }
        #pragma unroll
        for (int r = 0; r < 9; r++){
            int idx = t + 256*r;                // 2304
            if (idx < 2304){
                int c = idx/48, j = idx - c*48;
                ws[j*49 + c] = g_WqT[(g*48+c)*384 + h*48 + j];
            }
        }
        __syncthreads();
        if (js == 0 && t < 32){
            float s = 0.f;
            #pragma unroll 8
            for (int j = 0; j < 48; j++) s += bq[h*48+j]*kfT[j*34 + t];
            kb32[t] = s;
        }
        if (js >= 8 && t < 32){
            float s = 0.f;
            #pragma unroll 8
            for (int j = 0; j < 48; j++){ float v = kfT[j*34 + t]; s += v*v; }
            ss32[t] += s;
        }
        #pragma unroll
        for (int r = 0; r < 3; r++){
            int o = t + 256*r;                  // 768 = 48c * 16 keypairs
            int c = o >> 4, kp = o & 15;
            u64 acc = 0ull;
            #pragma unroll 8
            for (int j = 0; j < 48; j++){
                float w = ws[j*49 + c];
                acc = f2fma(*(const u64*)&kfT[j*34 + 2*kp], pk2(w, w), acc);
            }
            *(u64*)&mT[c*34 + 2*kp] = acc;
        }
        __syncthreads();
        #pragma unroll
        for (int r = 0; r < 6; r++){
            int idx = t + 256*r;
            if (idx < 1536){
                int k = idx/48, c = idx - k*48;
                g_M[(kbase + k)*DX + js*48 + c] = rnd_tf32(mT[c*34 + k]);
            }
        }
    }
    __syncthreads();
    float sp = g_sp[h];
    #pragma unroll
    for (int r = 0; r < 2; r++){
        int idx = t + 256*r;                    // 32*16 = 512
        int k = idx >> 4, cc = idx & 15;
        float v = (cc == 0) ? (kb32[k] - (12.f/sp)*ss32[k]) : 0.f;
        g_M[(kbase + k)*DX + DF + cc] = (cc == 0) ? rnd_tf32(v) : 0.f;
    }
}

// ============ shared GEMM core: 64 rows x 256 cols, mma.sync tf32 ===========
__device__ __forceinline__ void gemm_chunk(const float* As, const float* Bs,
                                           float acc[4][4][4], int wid, int lane){
    int g = lane >> 2, t4 = lane & 3;
    #pragma unroll
    for (int k8 = 0; k8 < 4; k8++){
        u32 au[4][4];
        #pragma unroll
        for (int mt = 0; mt < 4; mt++){
            const float* ap = As + (mt*16 + g)*36 + k8*8 + t4;
            au[mt][0] = __float_as_uint(ap[0]);
            au[mt][1] = __float_as_uint(ap[8*36]);
            au[mt][2] = __float_as_uint(ap[4]);
            au[mt][3] = __float_as_uint(ap[8*36+4]);
        }
        u32 bu[4][2];
        #pragma unroll
        for (int nt8 = 0; nt8 < 4; nt8++){
            const float* bp = Bs + (wid*32 + nt8*8 + g)*36 + k8*8 + t4;
            bu[nt8][0] = __float_as_uint(bp[0]);
            bu[nt8][1] = __float_as_uint(bp[4]);
        }
        #pragma unroll
        for (int mt = 0; mt < 4; mt++)
            #pragma unroll
            for (int nt8 = 0; nt8 < 4; nt8++)
                mma168(acc[mt][nt8], au[mt], bu[nt8]);
    }
}

// stage one K-chunk (A 64x32, B 256x32) into smem buffer via cp.async
__device__ __forceinline__ void stage_tile(int t, u32 sb, const float* Ag,
                                           const float* Bg, int kc, int strideAB){
    #pragma unroll
    for (int it = 0; it < 2; it++){
        int i = t + 256*it, row = i>>3, kq = (i&7)*4;
        cp16(sb + (u32)(row*36 + kq)*4, Ag + (size_t)row*strideAB + kc*32 + kq);
    }
    #pragma unroll
    for (int it = 0; it < 8; it++){
        int i = t + 256*it, row = i>>3, kq = (i&7)*4;
        cp16(sb + (u32)(2304 + row*36 + kq)*4, Bg + (size_t)row*strideAB + kc*32 + kq);
    }
    asm volatile("cp.async.commit_group;" ::: "memory");
}

// ===================== K2b: tf32 mma logits + softmax ======================
__global__ void __launch_bounds__(256) k2b_logits(){
    extern __shared__ float smp[];
    float* red  = smp + 23040;   // 512
    float* rmax = red + 512;     // 64
    float* rsum = rmax + 64;     // 64
    int t = threadIdx.x, wid = t>>5, lane = t&31;
    int g = lane>>2, t4 = lane&3;
    int qt = blockIdx.x, h = blockIdx.y, b = blockIdx.z;

    const float* Ag = g_xfeat + (size_t)(b*NQ + qt*64)*DX;
    const float* Bg = g_M     + (size_t)((b*HH+h)*NK)*DX;
    u32 sb = smem_u32(smp);

    float acc[4][4][4];
    #pragma unroll
    for (int mt = 0; mt < 4; mt++)
        #pragma unroll
        for (int nt8 = 0; nt8 < 4; nt8++)
            #pragma unroll
            for (int r = 0; r < 4; r++) acc[mt][nt8][r] = 0.f;

    stage_tile(t, sb, Ag, Bg, 0, DX);
    for (int kc = 0; kc < 17; kc++){
        int buf = kc & 1;
        if (kc + 1 < 17){
            stage_tile(t, sb + (u32)(((kc+1)&1)*11520)*4, Ag, Bg, kc+1, DX);
            asm volatile("cp.async.wait_group 1;" ::: "memory");
        } else {
            asm volatile("cp.async.wait_group 0;" ::: "memory");
        }
        __syncthreads();
        gemm_chunk(smp + buf*11520, smp + buf*11520 + 2304, acc, wid, lane);
        __syncthreads();
    }

    // ---- softmax ----
    #pragma unroll
    for (int mt = 0; mt < 4; mt++)
        #pragma unroll
        for (int i = 0; i < 2; i++){
            float m = -1e30f;
            #pragma unroll
            for (int nt8 = 0; nt8 < 4; nt8++)
                m = fmaxf(m, fmaxf(acc[mt][nt8][2*i], acc[mt][nt8][2*i+1]));
            m = fmaxf(m, __shfl_xor_sync(~0u, m, 1));
            m = fmaxf(m, __shfl_xor_sync(~0u, m, 2));
            if (t4 == 0) red[(mt*16 + g + i*8)*8 + wid] = m;
        }
    __syncthreads();
    if (t < 64){
        float m = red[t*8];
        #pragma unroll
        for (int j = 1; j < 8; j++) m = fmaxf(m, red[t*8+j]);
        rmax[t] = m;
    }
    __syncthreads();
    #pragma unroll
    for (int mt = 0; mt < 4; mt++)
        #pragma unroll
        for (int i = 0; i < 2; i++){
            float mm = rmax[mt*16 + g + i*8];
            float s = 0.f;
            #pragma unroll
            for (int nt8 = 0; nt8 < 4; nt8++){
                float e0 = __expf(acc[mt][nt8][2*i]   - mm);
                float e1 = __expf(acc[mt][nt8][2*i+1] - mm);
                acc[mt][nt8][2*i] = e0; acc[mt][nt8][2*i+1] = e1;
                s += e0 + e1;
            }
            s += __shfl_xor_sync(~0u, s, 1);
            s += __shfl_xor_sync(~0u, s, 2);
            if (t4 == 0) red[(mt*16 + g + i*8)*8 + wid] = s;
        }
    __syncthreads();
    if (t < 64){
        float s = red[t*8];
        #pragma unroll
        for (int j = 1; j < 8; j++) s += red[t*8+j];
        rsum[t] = 1.f/s;
    }
    __syncthreads();
    #pragma unroll
    for (int mt = 0; mt < 4; mt++)
        #pragma unroll
        for (int i = 0; i < 2; i++){
            int row = mt*16 + g + i*8;
            float inv = rsum[row];
            float* dst = g_attn + (size_t)(b*NQ + qt*64 + row)*2048 + h*NK + wid*32;
            #pragma unroll
            for (int nt8 = 0; nt8 < 4; nt8++){
                float2 o = make_float2(rnd_tf32(acc[mt][nt8][2*i]*inv),
                                       rnd_tf32(acc[mt][nt8][2*i+1]*inv));
                *(float2*)(dst + nt8*8 + t4*2) = o;
            }
        }
}

// ===================== K3: tf32 mma attn @ vprojT + residual ================
__global__ void __launch_bounds__(256) k3_av(const float* __restrict__ hidden,
                                             const float* __restrict__ bo,
                                             float* __restrict__ out){
    extern __shared__ float smp[];
    int t = threadIdx.x, wid = t>>5, lane = t&31;
    int g = lane>>2, t4 = lane&3;
    int nt = blockIdx.x, qt = blockIdx.y, b = blockIdx.z;

    const float* Ag = g_attn   + (size_t)(b*NQ + qt*64)*2048;
    const float* Bg = g_vprojT + (size_t)(b*768 + nt*256)*2048;
    u32 sb = smem_u32(smp);

    float acc[4][4][4];
    #pragma unroll
    for (int mt = 0; mt < 4; mt++)
        #pragma unroll
        for (int nt8 = 0; nt8 < 4; nt8++)
            #pragma unroll
            for (int r = 0; r < 4; r++) acc[mt][nt8][r] = 0.f;

    stage_tile(t, sb, Ag, Bg, 0, 2048);
    for (int kc = 0; kc < 64; kc++){
        int buf = kc & 1;
        if (kc + 1 < 64){
            stage_tile(t, sb + (u32)(((kc+1)&1)*11520)*4, Ag, Bg, kc+1, 2048);
            asm volatile("cp.async.wait_group 1;" ::: "memory");
        } else {
            asm volatile("cp.async.wait_group 0;" ::: "memory");
        }
        __syncthreads();
        gemm_chunk(smp + buf*11520, smp + buf*11520 + 2304, acc, wid, lane);
        __syncthreads();
    }

    #pragma unroll
    for (int mt = 0; mt < 4; mt++)
        #pragma unroll
        for (int i = 0; i < 2; i++){
            int row = qt*64 + mt*16 + g + i*8;
            const float* hb = hidden + (size_t)(b*NQ + row)*768;
            float*       ob = out    + (size_t)(b*NQ + row)*768;
            #pragma unroll
            for (int nt8 = 0; nt8 < 4; nt8++){
                int col = nt*256 + wid*32 + nt8*8 + t4*2;
                float2 hv = *(const float2*)(hb + col);
                float vx = acc[mt][nt8][2*i]   + hv.x;
                float vy = acc[mt][nt8][2*i+1] + hv.y;
                if ((col & 15) == 0) vx += bo[col >> 4];
                *(float2*)(ob + col) = make_float2(vx, vy);
            }
        }
}

// ===========================================================================
extern "C" void kernel_launch(void* const* d_in, const int* in_sizes, int n_in,
                              void* d_out, int out_size){
    const float* hidden = (const float*)d_in[0];
    const float* vision = (const float*)d_in[1];
    const float* lnw    = (const float*)d_in[2];
    const float* Wq     = (const float*)d_in[3];
    const float* bq     = (const float*)d_in[4];
    const float* Wkv    = (const float*)d_in[5];
    const float* bkv    = (const float*)d_in[6];
    const float* Wo     = (const float*)d_in[7];
    const float* bo     = (const float*)d_in[8];
    const float* daa    = (const float*)d_in[9];
    float* out = (float*)d_out;

    const int s1a = (768*18)*4;
    const int s1b = (11520 + 768*18)*4;
    const int s2x = (16*768 + 16)*4;
    const int s2b = (23040 + 512 + 64 + 64)*4;   // 94720
    const int s3  = (23040)*4;                   // 92160
    cudaFuncSetAttribute(k1a_kv,    cudaFuncAttributeMaxDynamicSharedMemorySize, s1a);
    cudaFuncSetAttribute(k1b_vproj, cudaFuncAttributeMaxDynamicSharedMemorySize, s1b);
    cudaFuncSetAttribute(k2x_xfeat, cudaFuncAttributeMaxDynamicSharedMemorySize, s2x);
    cudaFuncSetAttribute(k2b_logits,cudaFuncAttributeMaxDynamicSharedMemorySize, s2b);
    cudaFuncSetAttribute(k3_av,     cudaFuncAttributeMaxDynamicSharedMemorySize, s3);

    k0_prep   <<<128, 256>>>(Wq, Wkv, Wo, daa);
    k1a_kv    <<<dim3(NK/16, 3, BB), 256, s1a>>>(vision, bkv);
    k1b_vproj <<<dim3(3, HH, BB), 256, s1b>>>();
    k2x_xfeat <<<dim3(NQ/16, BB), 256, s2x>>>(hidden, lnw);
    k2m_M     <<<dim3(NK/32, HH, BB), 256>>>(bq);
    k2b_logits<<<dim3(NQ/64, HH, BB), 256, s2b>>>();
    k3_av     <<<dim3(3, NQ/64, BB), 256, s3>>>(hidden, bo, out);
}

// round 10
// speedup vs baseline: 2.1765x; 1.2292x over previous
#include <cuda_runtime.h>
#include <cuda_bf16.h>
#include <math.h>
#include <stdint.h>

#define BB 8
#define NQ 1024
#define NK 256
#define HH 8
#define DF 528
#define DFP 576
#define DX 544

typedef unsigned long long u64;
typedef unsigned int u32;

__constant__ int c_cg[11]    = {0,1,1,1,2,2,2,3,3,3,3};
__constant__ int c_comps[11] = {0,2,3,4,8,9,10,14,11,12,13};
__constant__ int c_grade[16] = {0,1,1,1,1,2,2,2,2,2,2,3,3,3,3,4};

__device__ float g_WqT [5*48*384];
__device__ float g_WkvT[5*48*768];
__device__ float g_WoT [5*384*48];
__device__ float g_sp  [8];
__device__ __nv_bfloat16 g_xfeat [(size_t)BB*NQ*DX];
__device__ __nv_bfloat16 g_M     [(size_t)BB*HH*NK*DX];
__device__ float         g_kfeatT[(size_t)BB*HH*NK*DFP];
__device__ float         g_vtmp  [(size_t)BB*HH*48*16*NK];
__device__ __nv_bfloat16 g_vprojT[(size_t)BB*768*2048];
__device__ __nv_bfloat16 g_attn  [(size_t)BB*NQ*2048];

__device__ __forceinline__ u64 pk2(float lo, float hi){
    u64 u; asm("mov.b64 %0,{%1,%2};" : "=l"(u) : "f"(lo), "f"(hi)); return u;
}
__device__ __forceinline__ void upk2(u64 u, float& lo, float& hi){
    asm("mov.b64 {%0,%1},%2;" : "=f"(lo), "=f"(hi) : "l"(u));
}
__device__ __forceinline__ u64 f2fma(u64 a, u64 b, u64 c){
    u64 d; asm("fma.rn.f32x2 %0,%1,%2,%3;" : "=l"(d) : "l"(a), "l"(b), "l"(c)); return d;
}
__device__ __forceinline__ u32 bf2(float lo, float hi){
    u32 r; asm("cvt.rn.bf16x2.f32 %0,%1,%2;" : "=r"(r) : "f"(hi), "f"(lo)); return r;
}
__device__ __forceinline__ u32 smem_u32(const void* p){
    u32 a; asm("{ .reg .u64 t; cvta.to.shared.u64 t, %1; cvt.u32.u64 %0, t; }" : "=r"(a) : "l"(p));
    return a;
}
__device__ __forceinline__ void mma16816(float* d, const u32* a, const u32* b){
    asm volatile("mma.sync.aligned.m16n8k16.row.col.f32.bf16.bf16.f32 "
        "{%0,%1,%2,%3},{%4,%5,%6,%7},{%8,%9},{%0,%1,%2,%3};"
        : "+f"(d[0]), "+f"(d[1]), "+f"(d[2]), "+f"(d[3])
        : "r"(a[0]), "r"(a[1]), "r"(a[2]), "r"(a[3]), "r"(b[0]), "r"(b[1]));
}
__device__ __forceinline__ void cp16(u32 sdst, const void* gsrc){
    asm volatile("cp.async.cg.shared.global [%0], [%1], 16;" :: "r"(sdst), "l"(gsrc));
}

// ===================== K0: weight transposes + softplus =====================
__global__ void k0_prep(const float* __restrict__ Wq, const float* __restrict__ Wkv,
                        const float* __restrict__ Wo, const float* __restrict__ daa){
    int stride = gridDim.x * blockDim.x;
    int gid = blockIdx.x * blockDim.x + threadIdx.x;
    for (int idx = gid; idx < 5*384*48; idx += stride){
        int g = idx/(384*48), rem = idx%(384*48), o = rem/48, i = rem%48;
        g_WqT[(g*48+i)*384+o] = Wq[idx];
    }
    for (int idx = gid; idx < 5*768*48; idx += stride){
        int g = idx/(768*48), rem = idx%(768*48), o = rem/48, i = rem%48;
        g_WkvT[(g*48+i)*768+o] = Wkv[idx];
    }
    for (int idx = gid; idx < 5*48*384; idx += stride){
        int g = idx/(48*384), rem = idx%(48*384), o = rem/384, i = rem%384;
        g_WoT[(g*384+i)*48+o] = Wo[idx];
    }
    if (gid < 8){
        float x = daa[gid];
        g_sp[gid] = (x > 20.f) ? x : log1pf(expf(x));
    }
}

// ========== K1a: kv projection; grid (ktile, s, b) -> kfeatT/vtmp ===========
__global__ void __launch_bounds__(256) k1a_kv(const float* __restrict__ vision,
                                              const float* __restrict__ bkv){
    extern __shared__ float sm1[];
    float* xT = sm1;            // [(c*48+in)][key16] pad 18
    int b = blockIdx.z, s = blockIdx.y, k0 = blockIdx.x*16, t = threadIdx.x;

    for (int idx = t; idx < 16*768; idx += 256){
        int key = idx/768, e = idx - key*768, in = e>>4, c = e&15;
        xT[(c*48+in)*18 + key] = vision[((size_t)(b*NK + k0 + key))*768 + e];
    }
    __syncthreads();

    const float INVS = 0.051031036307982884f;  // 1/sqrt(384)
    const int GR[16] = {0,1,1,1,1,2,2,2,2,2,2,3,3,3,3,4};

    int o = t + 256*s;
    float bias = bkv[o];
    const float* wb = g_WkvT + o;
    for (int kt = 0; kt < 4; kt++){
        u64 acc[2][16];
        #pragma unroll
        for (int kp = 0; kp < 2; kp++){
            acc[kp][0] = pk2(bias, bias);
            #pragma unroll
            for (int c = 1; c < 16; c++) acc[kp][c] = 0ull;
        }
        #pragma unroll 4
        for (int in = 0; in < 48; in++){
            float w0 = wb[(0*48+in)*768], w1 = wb[(1*48+in)*768];
            float w2 = wb[(2*48+in)*768], w3 = wb[(3*48+in)*768];
            float w4 = wb[(4*48+in)*768];
            u64 wv[5] = {pk2(w0,w0), pk2(w1,w1), pk2(w2,w2), pk2(w3,w3), pk2(w4,w4)};
            #pragma unroll
            for (int c = 0; c < 16; c++){
                const float* xp = xT + (c*48+in)*18 + kt*4;
                acc[0][c] = f2fma(*(const u64*)(xp    ), wv[GR[c]], acc[0][c]);
                acc[1][c] = f2fma(*(const u64*)(xp + 2), wv[GR[c]], acc[1][c]);
            }
        }
        if (o < 384){
            int h = o/48, i = o - h*48;
            float sp = g_sp[h], spc = sp*(2.f/48.f);
            size_t rb = (size_t)((b*HH+h)*NK + k0 + kt*4)*DFP;
            const int IC[8] = {0,2,3,4,8,9,10,14};
            #pragma unroll
            for (int js = 0; js < 8; js++)
                #pragma unroll
                for (int kp = 0; kp < 2; kp++){
                    float lo, hi; upk2(acc[kp][IC[js]], lo, hi);
                    g_kfeatT[rb + (size_t)(2*kp  )*DFP + js*48+i] = lo*INVS;
                    g_kfeatT[rb + (size_t)(2*kp+1)*DFP + js*48+i] = hi*INVS;
                }
            const int PC[3] = {11,12,13};
            #pragma unroll
            for (int jp = 0; jp < 3; jp++)
                #pragma unroll
                for (int kp = 0; kp < 2; kp++){
                    float lo, hi; upk2(acc[kp][PC[jp]], lo, hi);
                    g_kfeatT[rb + (size_t)(2*kp  )*DFP + 384+jp*48+i] = lo*spc;
                    g_kfeatT[rb + (size_t)(2*kp+1)*DFP + 384+jp*48+i] = hi*spc;
                }
        } else {
            int vc = o - 384, h = vc/48, i = vc - h*48;
            float* vb = g_vtmp + (size_t)(((b*HH+h)*48+i)*16)*NK + (k0 + kt*4);
            #pragma unroll
            for (int c = 0; c < 16; c++){
                *(u64*)&vb[(size_t)c*NK]     = acc[0][c];
                *(u64*)&vb[(size_t)c*NK + 2] = acc[1][c];
            }
        }
    }
}

// ========== K1b: vprojT[b][col768][kh2048] -> bf16 ==========================
__global__ void __launch_bounds__(256) k1b_vproj(){
    extern __shared__ float sm2[];
    float* w_s = sm2;            // [g][i*48+o48] 5*2304
    float* v_s = sm2 + 11520;    // [(i*16+c)][key16] pad 18
    int sl = blockIdx.x, h = blockIdx.y, b = blockIdx.z, t = threadIdx.x;

    for (int idx = t; idx < 11520; idx += 256){
        int g = idx/2304, r = idx - g*2304;
        w_s[idx] = g_WoT[(g*384 + h*48)*48 + r];
    }
    int j = sl*256 + t;
    int o48 = j>>4, c = j&15, g = c_grade[c];
    const size_t vbase = (size_t)((b*HH+h)*48)*16*NK;

    for (int kt = 0; kt < 16; kt++){
        __syncthreads();
        for (int idx = t; idx < 12288; idx += 256){
            int key = idx&15, rr = idx>>4;
            v_s[rr*18 + key] = g_vtmp[vbase + (size_t)rr*NK + kt*16 + key];
        }
        __syncthreads();
        u64 acc[8];
        #pragma unroll
        for (int kp = 0; kp < 8; kp++) acc[kp] = 0ull;
        #pragma unroll 4
        for (int i = 0; i < 48; i++){
            float ww = w_s[g*2304 + i*48 + o48];
            u64 w2 = pk2(ww, ww);
            const float* vp = v_s + (i*16+c)*18;
            #pragma unroll
            for (int kp = 0; kp < 8; kp++)
                acc[kp] = f2fma(*(const u64*)(vp + 2*kp), w2, acc[kp]);
        }
        u32* dst = (u32*)(g_vprojT + (size_t)(b*768 + j)*2048 + h*NK + kt*16);
        #pragma unroll
        for (int kp = 0; kp < 8; kp++){
            float lo, hi; upk2(acc[kp], lo, hi);
            dst[kp] = bf2(lo, hi);
        }
    }
}

// ============ K2x: rmsnorm + reorder -> xfeat [row][544] (bf16) =============
__global__ void __launch_bounds__(256) k2x_xfeat(const float* __restrict__ hidden,
                                                 const float* __restrict__ lnw){
    extern __shared__ float sx[];
    float* rows = sx;               // 16*768
    float* rsq  = sx + 16*768;      // 16
    int b = blockIdx.y, q0 = blockIdx.x*16, t = threadIdx.x;
    const float* hrow = hidden + (size_t)(b*NQ+q0)*768;
    for (int idx = t; idx < 16*768; idx += 256) rows[idx] = hrow[idx];
    __syncthreads();
    { int r = t>>4, sub = t&15; float s = 0.f;
      for (int e = sub; e < 768; e += 16){ float v = rows[r*768+e]; s += v*v; }
      s += __shfl_xor_sync(~0u, s, 1);
      s += __shfl_xor_sync(~0u, s, 2);
      s += __shfl_xor_sync(~0u, s, 4);
      s += __shfl_xor_sync(~0u, s, 8);
      if (sub == 0) rsq[r] = rsqrtf(s*(1.f/48.f) + 1e-6f);
    }
    __syncthreads();
    __nv_bfloat16* dst = g_xfeat + (size_t)(b*NQ+q0)*DX;
    for (int idx = t; idx < 16*DX; idx += 256){
        int r = idx/DX, d = idx - r*DX;
        float val;
        if (d < DF){
            int js = d/48, in = d - js*48;
            val = rows[r*768 + in*16 + c_comps[js]] * rsq[r] * lnw[in];
        } else val = (d == DF) ? 1.f : 0.f;
        dst[idx] = __float2bfloat16(val);
    }
}

// ======= K2m: M[b,h][k][544] (bf16) — 512 CTAs, 32 keys each ================
__global__ void __launch_bounds__(256) k2m_M(const float* __restrict__ bq){
    __shared__ float kfT[48*34];   // [j][key32] pad 34
    __shared__ float ws [48*49];   // [j][c] pad 49
    __shared__ float mT [48*34];   // [c][key32] pad 34
    __shared__ float kb32[32];
    __shared__ float ss32[32];
    int kt0 = blockIdx.x*32, h = blockIdx.y, b = blockIdx.z, t = threadIdx.x;
    size_t kbase = (size_t)((b*HH+h)*NK) + kt0;
    if (t < 32) ss32[t] = 0.f;

    for (int js = 0; js < 11; js++){
        int g = c_cg[js];
        __syncthreads();
        #pragma unroll
        for (int r = 0; r < 6; r++){
            int idx = t + 256*r;                // 48*32 = 1536
            if (idx < 1536){
                int k = idx/48, j = idx - k*48;
                kfT[j*34 + k] = g_kfeatT[(kbase + k)*DFP + js*48 + j];
            }
        }
        #pragma unroll
        for (int r = 0; r < 9; r++){
            int idx = t + 256*r;                // 2304
            if (idx < 2304){
                int c = idx/48, j = idx - c*48;
                ws[j*49 + c] = g_WqT[(g*48+c)*384 + h*48 + j];
            }
        }
        __syncthreads();
        if (js == 0 && t < 32){
            float s = 0.f;
            #pragma unroll 8
            for (int j = 0; j < 48; j++) s += bq[h*48+j]*kfT[j*34 + t];
            kb32[t] = s;
        }
        if (js >= 8 && t < 32){
            float s = 0.f;
            #pragma unroll 8
            for (int j = 0; j < 48; j++){ float v = kfT[j*34 + t]; s += v*v; }
            ss32[t] += s;
        }
        #pragma unroll
        for (int r = 0; r < 3; r++){
            int o = t + 256*r;                  // 768 = 48c * 16 keypairs
            int c = o >> 4, kp = o & 15;
            u64 acc = 0ull;
            #pragma unroll 8
            for (int j = 0; j < 48; j++){
                float w = ws[j*49 + c];
                acc = f2fma(*(const u64*)&kfT[j*34 + 2*kp], pk2(w, w), acc);
            }
            *(u64*)&mT[c*34 + 2*kp] = acc;
        }
        __syncthreads();
        #pragma unroll
        for (int r = 0; r < 6; r++){
            int idx = t + 256*r;
            if (idx < 1536){
                int k = idx/48, c = idx - k*48;
                g_M[(kbase + k)*DX + js*48 + c] = __float2bfloat16(mT[c*34 + k]);
            }
        }
    }
    __syncthreads();
    float sp = g_sp[h];
    #pragma unroll
    for (int r = 0; r < 2; r++){
        int idx = t + 256*r;                    // 32*16 = 512
        int k = idx >> 4, cc = idx & 15;
        float v = (cc == 0) ? (kb32[k] - (12.f/sp)*ss32[k]) : 0.f;
        g_M[(kbase + k)*DX + DF + cc] = __float2bfloat16(v);
    }
}

// ============ bf16 GEMM core: 64 rows x 256 cols, mma.sync m16n8k16 =========
// A tile: 64 rows x 32 bf16 (u32 stride 20); B tile: 256 rows x 32 bf16.
#define AROW 20
#define BOFF 1280
#define BUFU 6400

__device__ __forceinline__ void gemm_chunk(const u32* As, const u32* Bs,
                                           float acc[4][4][4], int wid, int lane){
    int g = lane >> 2, t4 = lane & 3;
    #pragma unroll
    for (int k16 = 0; k16 < 2; k16++){
        int ko = k16*8;
        u32 au[4][4];
        #pragma unroll
        for (int mt = 0; mt < 4; mt++){
            const u32* ap = As + (mt*16 + g)*AROW + ko + t4;
            au[mt][0] = ap[0];
            au[mt][1] = ap[8*AROW];
            au[mt][2] = ap[4];
            au[mt][3] = ap[8*AROW + 4];
        }
        u32 bu[4][2];
        #pragma unroll
        for (int nt8 = 0; nt8 < 4; nt8++){
            const u32* bp = Bs + (wid*32 + nt8*8 + g)*AROW + ko + t4;
            bu[nt8][0] = bp[0];
            bu[nt8][1] = bp[4];
        }
        #pragma unroll
        for (int mt = 0; mt < 4; mt++)
            #pragma unroll
            for (int nt8 = 0; nt8 < 4; nt8++)
                mma16816(acc[mt][nt8], au[mt], bu[nt8]);
    }
}

// stage one K-chunk (A 64x32, B 256x32 bf16) via cp.async
__device__ __forceinline__ void stage_tile(int t, u32 sb, const __nv_bfloat16* Ag,
                                           const __nv_bfloat16* Bg, int kc, int stride){
    { int row = t>>2, seg = t&3;
      cp16(sb + (u32)(row*AROW + seg*4)*4, Ag + (size_t)row*stride + kc*32 + seg*8); }
    #pragma unroll
    for (int it = 0; it < 4; it++){
        int i = t + 256*it, row = i>>2, seg = i&3;
        cp16(sb + (u32)(BOFF + row*AROW + seg*4)*4, Bg + (size_t)row*stride + kc*32 + seg*8);
    }
    asm volatile("cp.async.commit_group;" ::: "memory");
}

// ===================== K2b: bf16 mma logits + softmax ======================
__global__ void __launch_bounds__(256, 2) k2b_logits(){
    extern __shared__ u32 smp[];
    float* red  = (float*)(smp + 2*BUFU);   // 512
    float* rmax = red + 512;
    float* rsum = rmax + 64;
    int t = threadIdx.x, wid = t>>5, lane = t&31;
    int g = lane>>2, t4 = lane&3;
    int qt = blockIdx.x, h = blockIdx.y, b = blockIdx.z;

    const __nv_bfloat16* Ag = g_xfeat + (size_t)(b*NQ + qt*64)*DX;
    const __nv_bfloat16* Bg = g_M     + (size_t)((b*HH+h)*NK)*DX;
    u32 sb = smem_u32(smp);

    float acc[4][4][4];
    #pragma unroll
    for (int mt = 0; mt < 4; mt++)
        #pragma unroll
        for (int nt8 = 0; nt8 < 4; nt8++)
            #pragma unroll
            for (int r = 0; r < 4; r++) acc[mt][nt8][r] = 0.f;

    stage_tile(t, sb, Ag, Bg, 0, DX);
    for (int kc = 0; kc < 17; kc++){
        int buf = kc & 1;
        if (kc + 1 < 17){
            stage_tile(t, sb + (u32)(((kc+1)&1)*BUFU)*4, Ag, Bg, kc+1, DX);
            asm volatile("cp.async.wait_group 1;" ::: "memory");
        } else {
            asm volatile("cp.async.wait_group 0;" ::: "memory");
        }
        __syncthreads();
        gemm_chunk(smp + buf*BUFU, smp + buf*BUFU + BOFF, acc, wid, lane);
        __syncthreads();
    }

    // ---- softmax ----
    #pragma unroll
    for (int mt = 0; mt < 4; mt++)
        #pragma unroll
        for (int i = 0; i < 2; i++){
            float m = -1e30f;
            #pragma unroll
            for (int nt8 = 0; nt8 < 4; nt8++)
                m = fmaxf(m, fmaxf(acc[mt][nt8][2*i], acc[mt][nt8][2*i+1]));
            m = fmaxf(m, __shfl_xor_sync(~0u, m, 1));
            m = fmaxf(m, __shfl_xor_sync(~0u, m, 2));
            if (t4 == 0) red[(mt*16 + g + i*8)*8 + wid] = m;
        }
    __syncthreads();
    if (t < 64){
        float m = red[t*8];
        #pragma unroll
        for (int j = 1; j < 8; j++) m = fmaxf(m, red[t*8+j]);
        rmax[t] = m;
    }
    __syncthreads();
    #pragma unroll
    for (int mt = 0; mt < 4; mt++)
        #pragma unroll
        for (int i = 0; i < 2; i++){
            float mm = rmax[mt*16 + g + i*8];
            float s = 0.f;
            #pragma unroll
            for (int nt8 = 0; nt8 < 4; nt8++){
                float e0 = __expf(acc[mt][nt8][2*i]   - mm);
                float e1 = __expf(acc[mt][nt8][2*i+1] - mm);
                acc[mt][nt8][2*i] = e0; acc[mt][nt8][2*i+1] = e1;
                s += e0 + e1;
            }
            s += __shfl_xor_sync(~0u, s, 1);
            s += __shfl_xor_sync(~0u, s, 2);
            if (t4 == 0) red[(mt*16 + g + i*8)*8 + wid] = s;
        }
    __syncthreads();
    if (t < 64){
        float s = red[t*8];
        #pragma unroll
        for (int j = 1; j < 8; j++) s += red[t*8+j];
        rsum[t] = 1.f/s;
    }
    __syncthreads();
    #pragma unroll
    for (int mt = 0; mt < 4; mt++)
        #pragma unroll
        for (int i = 0; i < 2; i++){
            int row = mt*16 + g + i*8;
            float inv = rsum[row];
            __nv_bfloat16* dst = g_attn + (size_t)(b*NQ + qt*64 + row)*2048 + h*NK + wid*32;
            #pragma unroll
            for (int nt8 = 0; nt8 < 4; nt8++)
                *(u32*)(dst + nt8*8 + t4*2) = bf2(acc[mt][nt8][2*i]*inv,
                                                  acc[mt][nt8][2*i+1]*inv);
        }
}

// ===================== K3: bf16 mma attn @ vprojT + residual ================
__global__ void __launch_bounds__(256, 2) k3_av(const float* __restrict__ hidden,
                                                const float* __restrict__ bo,
                                                float* __restrict__ out){
    extern __shared__ u32 smp[];
    int t = threadIdx.x, wid = t>>5, lane = t&31;
    int g = lane>>2, t4 = lane&3;
    int nt = blockIdx.x, qt = blockIdx.y, b = blockIdx.z;

    const __nv_bfloat16* Ag = g_attn   + (size_t)(b*NQ + qt*64)*2048;
    const __nv_bfloat16* Bg = g_vprojT + (size_t)(b*768 + nt*256)*2048;
    u32 sb = smem_u32(smp);

    float acc[4][4][4];
    #pragma unroll
    for (int mt = 0; mt < 4; mt++)
        #pragma unroll
        for (int nt8 = 0; nt8 < 4; nt8++)
            #pragma unroll
            for (int r = 0; r < 4; r++) acc[mt][nt8][r] = 0.f;

    stage_tile(t, sb, Ag, Bg, 0, 2048);
    for (int kc = 0; kc < 64; kc++){
        int buf = kc & 1;
        if (kc + 1 < 64){
            stage_tile(t, sb + (u32)(((kc+1)&1)*BUFU)*4, Ag, Bg, kc+1, 2048);
            asm volatile("cp.async.wait_group 1;" ::: "memory");
        } else {
            asm volatile("cp.async.wait_group 0;" ::: "memory");
        }
        __syncthreads();
        gemm_chunk(smp + buf*BUFU, smp + buf*BUFU + BOFF, acc, wid, lane);
        __syncthreads();
    }

    #pragma unroll
    for (int mt = 0; mt < 4; mt++)
        #pragma unroll
        for (int i = 0; i < 2; i++){
            int row = qt*64 + mt*16 + g + i*8;
            const float* hb = hidden + (size_t)(b*NQ + row)*768;
            float*       ob = out    + (size_t)(b*NQ + row)*768;
            #pragma unroll
            for (int nt8 = 0; nt8 < 4; nt8++){
                int col = nt*256 + wid*32 + nt8*8 + t4*2;
                float2 hv = *(const float2*)(hb + col);
                float vx = acc[mt][nt8][2*i]   + hv.x;
                float vy = acc[mt][nt8][2*i+1] + hv.y;
                if ((col & 15) == 0) vx += bo[col >> 4];
                *(float2*)(ob + col) = make_float2(vx, vy);
            }
        }
}

// ===========================================================================
extern "C" void kernel_launch(void* const* d_in, const int* in_sizes, int n_in,
                              void* d_out, int out_size){
    const float* hidden = (const float*)d_in[0];
    const float* vision = (const float*)d_in[1];
    const float* lnw    = (const float*)d_in[2];
    const float* Wq     = (const float*)d_in[3];
    const float* bq     = (const float*)d_in[4];
    const float* Wkv    = (const float*)d_in[5];
    const float* bkv    = (const float*)d_in[6];
    const float* Wo     = (const float*)d_in[7];
    const float* bo     = (const float*)d_in[8];
    const float* daa    = (const float*)d_in[9];
    float* out = (float*)d_out;

    const int s1a = (768*18)*4;
    const int s1b = (11520 + 768*18)*4;
    const int s2x = (16*768 + 16)*4;
    const int s2b = (2*BUFU)*4 + (512 + 64 + 64)*4;   // 53760
    const int s3  = (2*BUFU)*4;                       // 51200
    cudaFuncSetAttribute(k1a_kv,    cudaFuncAttributeMaxDynamicSharedMemorySize, s1a);
    cudaFuncSetAttribute(k1b_vproj, cudaFuncAttributeMaxDynamicSharedMemorySize, s1b);
    cudaFuncSetAttribute(k2x_xfeat, cudaFuncAttributeMaxDynamicSharedMemorySize, s2x);
    cudaFuncSetAttribute(k2b_logits,cudaFuncAttributeMaxDynamicSharedMemorySize, s2b);
    cudaFuncSetAttribute(k3_av,     cudaFuncAttributeMaxDynamicSharedMemorySize, s3);

    k0_prep   <<<128, 256>>>(Wq, Wkv, Wo, daa);
    k1a_kv    <<<dim3(NK/16, 3, BB), 256, s1a>>>(vision, bkv);
    k1b_vproj <<<dim3(3, HH, BB), 256, s1b>>>();
    k2x_xfeat <<<dim3(NQ/16, BB), 256, s2x>>>(hidden, lnw);
    k2m_M     <<<dim3(NK/32, HH, BB), 256>>>(bq);
    k2b_logits<<<dim3(NQ/64, HH, BB), 256, s2b>>>();
    k3_av     <<<dim3(3, NQ/64, BB), 256, s3>>>(hidden, bo, out);
}

// round 11
// speedup vs baseline: 2.2112x; 1.0159x over previous
#include <cuda_runtime.h>
#include <cuda_bf16.h>
#include <math.h>
#include <stdint.h>

#define BB 8
#define NQ 1024
#define NK 256
#define HH 8
#define DF 528
#define DFP 576
#define DX 544

typedef unsigned long long u64;
typedef unsigned int u32;

__constant__ int c_cg[11]    = {0,1,1,1,2,2,2,3,3,3,3};
__constant__ int c_comps[11] = {0,2,3,4,8,9,10,14,11,12,13};
__constant__ int c_grade[16] = {0,1,1,1,1,2,2,2,2,2,2,3,3,3,3,4};

__device__ float g_WqT [5*48*384];
__device__ float g_WkvT[5*48*768];
__device__ float g_WoT [5*384*48];
__device__ float g_sp  [8];
__device__ __nv_bfloat16 g_xfeat [(size_t)BB*NQ*DX];
__device__ __nv_bfloat16 g_M     [(size_t)BB*HH*NK*DX];
__device__ float         g_kfeatT[(size_t)BB*HH*NK*DFP];
__device__ float         g_vtmp  [(size_t)BB*HH*48*16*NK];
__device__ __nv_bfloat16 g_vprojT[(size_t)BB*768*2048];
__device__ __nv_bfloat16 g_attn  [(size_t)BB*NQ*2048];

__device__ __forceinline__ u64 pk2(float lo, float hi){
    u64 u; asm("mov.b64 %0,{%1,%2};" : "=l"(u) : "f"(lo), "f"(hi)); return u;
}
__device__ __forceinline__ void upk2(u64 u, float& lo, float& hi){
    asm("mov.b64 {%0,%1},%2;" : "=f"(lo), "=f"(hi) : "l"(u));
}
__device__ __forceinline__ u64 f2fma(u64 a, u64 b, u64 c){
    u64 d; asm("fma.rn.f32x2 %0,%1,%2,%3;" : "=l"(d) : "l"(a), "l"(b), "l"(c)); return d;
}
__device__ __forceinline__ u32 bf2(float lo, float hi){
    u32 r; asm("cvt.rn.bf16x2.f32 %0,%1,%2;" : "=r"(r) : "f"(hi), "f"(lo)); return r;
}
__device__ __forceinline__ u32 smem_u32(const void* p){
    u32 a; asm("{ .reg .u64 t; cvta.to.shared.u64 t, %1; cvt.u32.u64 %0, t; }" : "=r"(a) : "l"(p));
    return a;
}
__device__ __forceinline__ void mma16816(float* d, const u32* a, const u32* b){
    asm volatile("mma.sync.aligned.m16n8k16.row.col.f32.bf16.bf16.f32 "
        "{%0,%1,%2,%3},{%4,%5,%6,%7},{%8,%9},{%0,%1,%2,%3};"
        : "+f"(d[0]), "+f"(d[1]), "+f"(d[2]), "+f"(d[3])
        : "r"(a[0]), "r"(a[1]), "r"(a[2]), "r"(a[3]), "r"(b[0]), "r"(b[1]));
}
__device__ __forceinline__ void ldsm4(u32& r0, u32& r1, u32& r2, u32& r3, u32 addr){
    asm volatile("ldmatrix.sync.aligned.m8n8.x4.shared.b16 {%0,%1,%2,%3},[%4];"
        : "=r"(r0), "=r"(r1), "=r"(r2), "=r"(r3) : "r"(addr));
}
__device__ __forceinline__ void cp16(u32 sdst, const void* gsrc){
    asm volatile("cp.async.cg.shared.global [%0], [%1], 16;" :: "r"(sdst), "l"(gsrc));
}

// ============ K0x: weight transposes + softplus + rmsnorm/xfeat =============
__global__ void __launch_bounds__(256) k0x_prep(const float* __restrict__ Wq,
                        const float* __restrict__ Wkv, const float* __restrict__ Wo,
                        const float* __restrict__ daa, const float* __restrict__ hidden,
                        const float* __restrict__ lnw){
    extern __shared__ float sx[];
    float* rows = sx;               // 16*768
    float* rsq  = sx + 16*768;      // 16
    int t = threadIdx.x;
    int gid = blockIdx.x * blockDim.x + t;
    int stride = gridDim.x * blockDim.x;
    for (int idx = gid; idx < 5*384*48; idx += stride){
        int g = idx/(384*48), rem = idx%(384*48), o = rem/48, i = rem%48;
        g_WqT[(g*48+i)*384+o] = Wq[idx];
    }
    for (int idx = gid; idx < 5*768*48; idx += stride){
        int g = idx/(768*48), rem = idx%(768*48), o = rem/48, i = rem%48;
        g_WkvT[(g*48+i)*768+o] = Wkv[idx];
    }
    for (int idx = gid; idx < 5*48*384; idx += stride){
        int g = idx/(48*384), rem = idx%(48*384), o = rem/384, i = rem%384;
        g_WoT[(g*384+i)*48+o] = Wo[idx];
    }
    if (gid < 8){
        float x = daa[gid];
        g_sp[gid] = (x > 20.f) ? x : log1pf(expf(x));
    }

    // ---- k2x part: blockIdx.x -> (b, q0) ----
    int b = blockIdx.x >> 6, q0 = (blockIdx.x & 63)*16;
    const float* hrow = hidden + (size_t)(b*NQ+q0)*768;
    for (int idx = t; idx < 16*768; idx += 256) rows[idx] = hrow[idx];
    __syncthreads();
    { int r = t>>4, sub = t&15; float s = 0.f;
      for (int e = sub; e < 768; e += 16){ float v = rows[r*768+e]; s += v*v; }
      s += __shfl_xor_sync(~0u, s, 1);
      s += __shfl_xor_sync(~0u, s, 2);
      s += __shfl_xor_sync(~0u, s, 4);
      s += __shfl_xor_sync(~0u, s, 8);
      if (sub == 0) rsq[r] = rsqrtf(s*(1.f/48.f) + 1e-6f);
    }
    __syncthreads();
    __nv_bfloat16* dst = g_xfeat + (size_t)(b*NQ+q0)*DX;
    for (int idx = t; idx < 16*DX; idx += 256){
        int r = idx/DX, d = idx - r*DX;
        float val;
        if (d < DF){
            int js = d/48, in = d - js*48;
            val = rows[r*768 + in*16 + c_comps[js]] * rsq[r] * lnw[in];
        } else val = (d == DF) ? 1.f : 0.f;
        dst[idx] = __float2bfloat16(val);
    }
}

// ========== K1a: kv projection; grid (ktile, s, b) -> kfeatT/vtmp ===========
__global__ void __launch_bounds__(256) k1a_kv(const float* __restrict__ vision,
                                              const float* __restrict__ bkv){
    extern __shared__ float sm1[];
    float* xT = sm1;            // [(c*48+in)][key16] pad 18
    int b = blockIdx.z, s = blockIdx.y, k0 = blockIdx.x*16, t = threadIdx.x;

    for (int idx = t; idx < 16*768; idx += 256){
        int key = idx/768, e = idx - key*768, in = e>>4, c = e&15;
        xT[(c*48+in)*18 + key] = vision[((size_t)(b*NK + k0 + key))*768 + e];
    }
    __syncthreads();

    const float INVS = 0.051031036307982884f;  // 1/sqrt(384)
    const int GR[16] = {0,1,1,1,1,2,2,2,2,2,2,3,3,3,3,4};

    int o = t + 256*s;
    float bias = bkv[o];
    const float* wb = g_WkvT + o;
    for (int kt = 0; kt < 4; kt++){
        u64 acc[2][16];
        #pragma unroll
        for (int kp = 0; kp < 2; kp++){
            acc[kp][0] = pk2(bias, bias);
            #pragma unroll
            for (int c = 1; c < 16; c++) acc[kp][c] = 0ull;
        }
        #pragma unroll 4
        for (int in = 0; in < 48; in++){
            float w0 = wb[(0*48+in)*768], w1 = wb[(1*48+in)*768];
            float w2 = wb[(2*48+in)*768], w3 = wb[(3*48+in)*768];
            float w4 = wb[(4*48+in)*768];
            u64 wv[5] = {pk2(w0,w0), pk2(w1,w1), pk2(w2,w2), pk2(w3,w3), pk2(w4,w4)};
            #pragma unroll
            for (int c = 0; c < 16; c++){
                const float* xp = xT + (c*48+in)*18 + kt*4;
                acc[0][c] = f2fma(*(const u64*)(xp    ), wv[GR[c]], acc[0][c]);
                acc[1][c] = f2fma(*(const u64*)(xp + 2), wv[GR[c]], acc[1][c]);
            }
        }
        if (o < 384){
            int h = o/48, i = o - h*48;
            float sp = g_sp[h], spc = sp*(2.f/48.f);
            size_t rb = (size_t)((b*HH+h)*NK + k0 + kt*4)*DFP;
            const int IC[8] = {0,2,3,4,8,9,10,14};
            #pragma unroll
            for (int js = 0; js < 8; js++)
                #pragma unroll
                for (int kp = 0; kp < 2; kp++){
                    float lo, hi; upk2(acc[kp][IC[js]], lo, hi);
                    g_kfeatT[rb + (size_t)(2*kp  )*DFP + js*48+i] = lo*INVS;
                    g_kfeatT[rb + (size_t)(2*kp+1)*DFP + js*48+i] = hi*INVS;
                }
            const int PC[3] = {11,12,13};
            #pragma unroll
            for (int jp = 0; jp < 3; jp++)
                #pragma unroll
                for (int kp = 0; kp < 2; kp++){
                    float lo, hi; upk2(acc[kp][PC[jp]], lo, hi);
                    g_kfeatT[rb + (size_t)(2*kp  )*DFP + 384+jp*48+i] = lo*spc;
                    g_kfeatT[rb + (size_t)(2*kp+1)*DFP + 384+jp*48+i] = hi*spc;
                }
        } else {
            int vc = o - 384, h = vc/48, i = vc - h*48;
            float* vb = g_vtmp + (size_t)(((b*HH+h)*48+i)*16)*NK + (k0 + kt*4);
            #pragma unroll
            for (int c = 0; c < 16; c++){
                *(u64*)&vb[(size_t)c*NK]     = acc[0][c];
                *(u64*)&vb[(size_t)c*NK + 2] = acc[1][c];
            }
        }
    }
}

// ========== K1b: vprojT[b][col768][kh2048] -> bf16 ==========================
__global__ void __launch_bounds__(256) k1b_vproj(){
    extern __shared__ float sm2[];
    float* w_s = sm2;            // [g][i*48+o48] 5*2304
    float* v_s = sm2 + 11520;    // [(i*16+c)][key16] pad 18
    int sl = blockIdx.x, h = blockIdx.y, b = blockIdx.z, t = threadIdx.x;

    for (int idx = t; idx < 11520; idx += 256){
        int g = idx/2304, r = idx - g*2304;
        w_s[idx] = g_WoT[(g*384 + h*48)*48 + r];
    }
    int j = sl*256 + t;
    int o48 = j>>4, c = j&15, g = c_grade[c];
    const size_t vbase = (size_t)((b*HH+h)*48)*16*NK;

    for (int kt = 0; kt < 16; kt++){
        __syncthreads();
        for (int idx = t; idx < 12288; idx += 256){
            int key = idx&15, rr = idx>>4;
            v_s[rr*18 + key] = g_vtmp[vbase + (size_t)rr*NK + kt*16 + key];
        }
        __syncthreads();
        u64 acc[8];
        #pragma unroll
        for (int kp = 0; kp < 8; kp++) acc[kp] = 0ull;
        #pragma unroll 4
        for (int i = 0; i < 48; i++){
            float ww = w_s[g*2304 + i*48 + o48];
            u64 w2 = pk2(ww, ww);
            const float* vp = v_s + (i*16+c)*18;
            #pragma unroll
            for (int kp = 0; kp < 8; kp++)
                acc[kp] = f2fma(*(const u64*)(vp + 2*kp), w2, acc[kp]);
        }
        u32* dst = (u32*)(g_vprojT + (size_t)(b*768 + j)*2048 + h*NK + kt*16);
        #pragma unroll
        for (int kp = 0; kp < 8; kp++){
            float lo, hi; upk2(acc[kp], lo, hi);
            dst[kp] = bf2(lo, hi);
        }
    }
}

// ======= K2m: M[b,h][k][544] (bf16) — 512 CTAs, 32 keys each ================
__global__ void __launch_bounds__(256) k2m_M(const float* __restrict__ bq){
    __shared__ float kfT[48*34];   // [j][key32] pad 34
    __shared__ float ws [48*49];   // [j][c] pad 49
    __shared__ float mT [48*34];   // [c][key32] pad 34
    __shared__ float kb32[32];
    __shared__ float ss32[32];
    int kt0 = blockIdx.x*32, h = blockIdx.y, b = blockIdx.z, t = threadIdx.x;
    size_t kbase = (size_t)((b*HH+h)*NK) + kt0;
    if (t < 32) ss32[t] = 0.f;

    for (int js = 0; js < 11; js++){
        int g = c_cg[js];
        __syncthreads();
        #pragma unroll
        for (int r = 0; r < 6; r++){
            int idx = t + 256*r;                // 48*32 = 1536
            if (idx < 1536){
                int k = idx/48, j = idx - k*48;
                kfT[j*34 + k] = g_kfeatT[(kbase + k)*DFP + js*48 + j];
            }
        }
        #pragma unroll
        for (int r = 0; r < 9; r++){
            int idx = t + 256*r;                // 2304
            if (idx < 2304){
                int c = idx/48, j = idx - c*48;
                ws[j*49 + c] = g_WqT[(g*48+c)*384 + h*48 + j];
            }
        }
        __syncthreads();
        if (js == 0 && t < 32){
            float s = 0.f;
            #pragma unroll 8
            for (int j = 0; j < 48; j++) s += bq[h*48+j]*kfT[j*34 + t];
            kb32[t] = s;
        }
        if (js >= 8 && t < 32){
            float s = 0.f;
            #pragma unroll 8
            for (int j = 0; j < 48; j++){ float v = kfT[j*34 + t]; s += v*v; }
            ss32[t] += s;
        }
        #pragma unroll
        for (int r = 0; r < 3; r++){
            int o = t + 256*r;                  // 768 = 48c * 16 keypairs
            int c = o >> 4, kp = o & 15;
            u64 acc = 0ull;
            #pragma unroll 8
            for (int j = 0; j < 48; j++){
                float w = ws[j*49 + c];
                acc = f2fma(*(const u64*)&kfT[j*34 + 2*kp], pk2(w, w), acc);
            }
            *(u64*)&mT[c*34 + 2*kp] = acc;
        }
        __syncthreads();
        #pragma unroll
        for (int r = 0; r < 6; r++){
            int idx = t + 256*r;
            if (idx < 1536){
                int k = idx/48, c = idx - k*48;
                g_M[(kbase + k)*DX + js*48 + c] = __float2bfloat16(mT[c*34 + k]);
            }
        }
    }
    __syncthreads();
    float sp = g_sp[h];
    #pragma unroll
    for (int r = 0; r < 2; r++){
        int idx = t + 256*r;                    // 32*16 = 512
        int k = idx >> 4, cc = idx & 15;
        float v = (cc == 0) ? (kb32[k] - (12.f/sp)*ss32[k]) : 0.f;
        g_M[(kbase + k)*DX + DF + cc] = __float2bfloat16(v);
    }
}

// ============ bf16 GEMM core: 64 rows x 256 cols, ldmatrix + mma16816 =======
#define AROW 20
#define BOFF 1280
#define BUFU 6400

__device__ __forceinline__ void gemm_chunk(u32 base, float acc[4][4][4],
                                           int wid, u32 aofs, u32 bofs){
    #pragma unroll
    for (int k16 = 0; k16 < 2; k16++){
        int ko = k16*8;
        u32 au[4][4];
        #pragma unroll
        for (int mt = 0; mt < 4; mt++)
            ldsm4(au[mt][0], au[mt][1], au[mt][2], au[mt][3],
                  base + (u32)(mt*16*AROW + ko)*4 + aofs);
        u32 bu[4][2];
        ldsm4(bu[0][0], bu[0][1], bu[1][0], bu[1][1],
              base + (u32)(BOFF + wid*32*AROW + ko)*4 + bofs);
        ldsm4(bu[2][0], bu[2][1], bu[3][0], bu[3][1],
              base + (u32)(BOFF + (wid*32+16)*AROW + ko)*4 + bofs);
        #pragma unroll
        for (int mt = 0; mt < 4; mt++)
            #pragma unroll
            for (int nt8 = 0; nt8 < 4; nt8++)
                mma16816(acc[mt][nt8], au[mt], bu[nt8]);
    }
}

// stage one K-chunk (A 64x32, B 256x32 bf16) via cp.async
__device__ __forceinline__ void stage_tile(int t, u32 sb, const __nv_bfloat16* Ag,
                                           const __nv_bfloat16* Bg, int kc, int stride){
    { int row = t>>2, seg = t&3;
      cp16(sb + (u32)(row*AROW + seg*4)*4, Ag + (size_t)row*stride + kc*32 + seg*8); }
    #pragma unroll
    for (int it = 0; it < 4; it++){
        int i = t + 256*it, row = i>>2, seg = i&3;
        cp16(sb + (u32)(BOFF + row*AROW + seg*4)*4, Bg + (size_t)row*stride + kc*32 + seg*8);
    }
    asm volatile("cp.async.commit_group;" ::: "memory");
}

// ===================== K2b: bf16 mma logits + softmax ======================
__global__ void __launch_bounds__(256, 2) k2b_logits(){
    extern __shared__ u32 smp[];
    float* red  = (float*)(smp + 3*BUFU);   // 512
    float* rmax = red + 512;
    float* rsum = rmax + 64;
    int t = threadIdx.x, wid = t>>5, lane = t&31;
    int g = lane>>2, t4 = lane&3;
    int qt = blockIdx.x, h = blockIdx.y, b = blockIdx.z;

    u32 aofs = (u32)((((lane&7) + ((lane>>3)&1)*8)*AROW + ((lane>>4)&1)*4)*4);
    u32 bofs = (u32)(((((lane>>4)&1)*8 + (lane&7))*AROW + ((lane>>3)&1)*4)*4);

    const __nv_bfloat16* Ag = g_xfeat + (size_t)(b*NQ + qt*64)*DX;
    const __nv_bfloat16* Bg = g_M     + (size_t)((b*HH+h)*NK)*DX;
    u32 sb = smem_u32(smp);

    float acc[4][4][4];
    #pragma unroll
    for (int mt = 0; mt < 4; mt++)
        #pragma unroll
        for (int nt8 = 0; nt8 < 4; nt8++)
            #pragma unroll
            for (int r = 0; r < 4; r++) acc[mt][nt8][r] = 0.f;

    stage_tile(t, sb, Ag, Bg, 0, DX);
    stage_tile(t, sb + BUFU*4, Ag, Bg, 1, DX);
    for (int kc = 0; kc < 17; kc++){
        asm volatile("cp.async.wait_group 1;" ::: "memory");
        __syncthreads();
        if (kc + 2 < 17)
            stage_tile(t, sb + (u32)(((kc+2)%3)*BUFU)*4, Ag, Bg, kc+2, DX);
        else
            asm volatile("cp.async.commit_group;" ::: "memory");
        gemm_chunk(sb + (u32)((kc%3)*BUFU)*4, acc, wid, aofs, bofs);
    }

    // ---- softmax ----
    __syncthreads();
    #pragma unroll
    for (int mt = 0; mt < 4; mt++)
        #pragma unroll
        for (int i = 0; i < 2; i++){
            float m = -1e30f;
            #pragma unroll
            for (int nt8 = 0; nt8 < 4; nt8++)
                m = fmaxf(m, fmaxf(acc[mt][nt8][2*i], acc[mt][nt8][2*i+1]));
            m = fmaxf(m, __shfl_xor_sync(~0u, m, 1));
            m = fmaxf(m, __shfl_xor_sync(~0u, m, 2));
            if (t4 == 0) red[(mt*16 + g + i*8)*8 + wid] = m;
        }
    __syncthreads();
    if (t < 64){
        float m = red[t*8];
        #pragma unroll
        for (int j = 1; j < 8; j++) m = fmaxf(m, red[t*8+j]);
        rmax[t] = m;
    }
    __syncthreads();
    #pragma unroll
    for (int mt = 0; mt < 4; mt++)
        #pragma unroll
        for (int i = 0; i < 2; i++){
            float mm = rmax[mt*16 + g + i*8];
            float s = 0.f;
            #pragma unroll
            for (int nt8 = 0; nt8 < 4; nt8++){
                float e0 = __expf(acc[mt][nt8][2*i]   - mm);
                float e1 = __expf(acc[mt][nt8][2*i+1] - mm);
                acc[mt][nt8][2*i] = e0; acc[mt][nt8][2*i+1] = e1;
                s += e0 + e1;
            }
            s += __shfl_xor_sync(~0u, s, 1);
            s += __shfl_xor_sync(~0u, s, 2);
            if (t4 == 0) red[(mt*16 + g + i*8)*8 + wid] = s;
        }
    __syncthreads();
    if (t < 64){
        float s = red[t*8];
        #pragma unroll
        for (int j = 1; j < 8; j++) s += red[t*8+j];
        rsum[t] = 1.f/s;
    }
    __syncthreads();
    #pragma unroll
    for (int mt = 0; mt < 4; mt++)
        #pragma unroll
        for (int i = 0; i < 2; i++){
            int row = mt*16 + g + i*8;
            float inv = rsum[row];
            __nv_bfloat16* dst = g_attn + (size_t)(b*NQ + qt*64 + row)*2048 + h*NK + wid*32;
            #pragma unroll
            for (int nt8 = 0; nt8 < 4; nt8++)
                *(u32*)(dst + nt8*8 + t4*2) = bf2(acc[mt][nt8][2*i]*inv,
                                                  acc[mt][nt8][2*i+1]*inv);
        }
}

// ===================== K3: bf16 mma attn @ vprojT + residual ================
__global__ void __launch_bounds__(256, 2) k3_av(const float* __restrict__ hidden,
                                                const float* __restrict__ bo,
                                                float* __restrict__ out){
    extern __shared__ u32 smp[];
    int t = threadIdx.x, wid = t>>5, lane = t&31;
    int g = lane>>2, t4 = lane&3;
    int nt = blockIdx.x, qt = blockIdx.y, b = blockIdx.z;

    u32 aofs = (u32)((((lane&7) + ((lane>>3)&1)*8)*AROW + ((lane>>4)&1)*4)*4);
    u32 bofs = (u32)(((((lane>>4)&1)*8 + (lane&7))*AROW + ((lane>>3)&1)*4)*4);

    const __nv_bfloat16* Ag = g_attn   + (size_t)(b*NQ + qt*64)*2048;
    const __nv_bfloat16* Bg = g_vprojT + (size_t)(b*768 + nt*256)*2048;
    u32 sb = smem_u32(smp);

    float acc[4][4][4];
    #pragma unroll
    for (int mt = 0; mt < 4; mt++)
        #pragma unroll
        for (int nt8 = 0; nt8 < 4; nt8++)
            #pragma unroll
            for (int r = 0; r < 4; r++) acc[mt][nt8][r] = 0.f;

    stage_tile(t, sb, Ag, Bg, 0, 2048);
    stage_tile(t, sb + BUFU*4, Ag, Bg, 1, 2048);
    for (int kc = 0; kc < 64; kc++){
        asm volatile("cp.async.wait_group 1;" ::: "memory");
        __syncthreads();
        if (kc + 2 < 64)
            stage_tile(t, sb + (u32)(((kc+2)%3)*BUFU)*4, Ag, Bg, kc+2, 2048);
        else
            asm volatile("cp.async.commit_group;" ::: "memory");
        gemm_chunk(sb + (u32)((kc%3)*BUFU)*4, acc, wid, aofs, bofs);
    }

    #pragma unroll
    for (int mt = 0; mt < 4; mt++)
        #pragma unroll
        for (int i = 0; i < 2; i++){
            int row = qt*64 + mt*16 + g + i*8;
            const float* hb = hidden + (size_t)(b*NQ + row)*768;
            float*       ob = out    + (size_t)(b*NQ + row)*768;
            #pragma unroll
            for (int nt8 = 0; nt8 < 4; nt8++){
                int col = nt*256 + wid*32 + nt8*8 + t4*2;
                float2 hv = *(const float2*)(hb + col);
                float vx = acc[mt][nt8][2*i]   + hv.x;
                float vy = acc[mt][nt8][2*i+1] + hv.y;
                if ((col & 15) == 0) vx += bo[col >> 4];
                *(float2*)(ob + col) = make_float2(vx, vy);
            }
        }
}

// ===========================================================================
extern "C" void kernel_launch(void* const* d_in, const int* in_sizes, int n_in,
                              void* d_out, int out_size){
    const float* hidden = (const float*)d_in[0];
    const float* vision = (const float*)d_in[1];
    const float* lnw    = (const float*)d_in[2];
    const float* Wq     = (const float*)d_in[3];
    const float* bq     = (const float*)d_in[4];
    const float* Wkv    = (const float*)d_in[5];
    const float* bkv    = (const float*)d_in[6];
    const float* Wo     = (const float*)d_in[7];
    const float* bo     = (const float*)d_in[8];
    const float* daa    = (const float*)d_in[9];
    float* out = (float*)d_out;

    const int s0x = (16*768 + 16)*4;
    const int s1a = (768*18)*4;
    const int s1b = (11520 + 768*18)*4;
    const int s2b = (3*BUFU)*4 + (512 + 64 + 64)*4;   // 79360
    const int s3  = (3*BUFU)*4;                        // 76800
    cudaFuncSetAttribute(k0x_prep,  cudaFuncAttributeMaxDynamicSharedMemorySize, s0x);
    cudaFuncSetAttribute(k1a_kv,    cudaFuncAttributeMaxDynamicSharedMemorySize, s1a);
    cudaFuncSetAttribute(k1b_vproj, cudaFuncAttributeMaxDynamicSharedMemorySize, s1b);
    cudaFuncSetAttribute(k2b_logits,cudaFuncAttributeMaxDynamicSharedMemorySize, s2b);
    cudaFuncSetAttribute(k3_av,     cudaFuncAttributeMaxDynamicSharedMemorySize, s3);

    k0x_prep  <<<512, 256, s0x>>>(Wq, Wkv, Wo, daa, hidden, lnw);
    k1a_kv    <<<dim3(NK/16, 3, BB), 256, s1a>>>(vision, bkv);
    k2m_M     <<<dim3(NK/32, HH, BB), 256>>>(bq);
    k2b_logits<<<dim3(NQ/64, HH, BB), 256, s2b>>>();
    k1b_vproj <<<dim3(3, HH, BB), 256, s1b>>>();
    k3_av     <<<dim3(3, NQ/64, BB), 256, s3>>>(hidden, bo, out);
}

// round 12
// speedup vs baseline: 2.6723x; 1.2085x over previous
#include <cuda_runtime.h>
#include <cuda_bf16.h>
#include <math.h>
#include <stdint.h>

#define BB 8
#define NQ 1024
#define NK 256
#define HH 8
#define DF 528
#define DFP 576
#define DX 544

typedef unsigned long long u64;
typedef unsigned int u32;

__constant__ int c_cg[11]    = {0,1,1,1,2,2,2,3,3,3,3};
__constant__ int c_comps[11] = {0,2,3,4,8,9,10,14,11,12,13};
__constant__ int c_grade[16] = {0,1,1,1,1,2,2,2,2,2,2,3,3,3,3,4};

__device__ float g_WqT [5*48*384];
__device__ float g_WkvT[5*48*768];
__device__ float g_WoT [5*384*48];
__device__ float g_sp  [8];
__device__ __nv_bfloat16 g_xfeat [(size_t)BB*NQ*DX];
__device__ __nv_bfloat16 g_M     [(size_t)BB*HH*NK*DX];
__device__ float         g_kfeatT[(size_t)BB*HH*NK*DFP];
__device__ float         g_vtmp  [(size_t)BB*HH*16*12288];
__device__ __nv_bfloat16 g_vprojT[(size_t)BB*768*2048];
__device__ __nv_bfloat16 g_attn  [(size_t)BB*NQ*2048];

__device__ __forceinline__ u64 pk2(float lo, float hi){
    u64 u; asm("mov.b64 %0,{%1,%2};" : "=l"(u) : "f"(lo), "f"(hi)); return u;
}
__device__ __forceinline__ void upk2(u64 u, float& lo, float& hi){
    asm("mov.b64 {%0,%1},%2;" : "=f"(lo), "=f"(hi) : "l"(u));
}
__device__ __forceinline__ u64 f2fma(u64 a, u64 b, u64 c){
    u64 d; asm("fma.rn.f32x2 %0,%1,%2,%3;" : "=l"(d) : "l"(a), "l"(b), "l"(c)); return d;
}
__device__ __forceinline__ u32 bf2(float lo, float hi){
    u32 r; asm("cvt.rn.bf16x2.f32 %0,%1,%2;" : "=r"(r) : "f"(hi), "f"(lo)); return r;
}
__device__ __forceinline__ u32 smem_u32(const void* p){
    u32 a; asm("{ .reg .u64 t; cvta.to.shared.u64 t, %1; cvt.u32.u64 %0, t; }" : "=r"(a) : "l"(p));
    return a;
}
__device__ __forceinline__ void mma16816(float* d, const u32* a, const u32* b){
    asm volatile("mma.sync.aligned.m16n8k16.row.col.f32.bf16.bf16.f32 "
        "{%0,%1,%2,%3},{%4,%5,%6,%7},{%8,%9},{%0,%1,%2,%3};"
        : "+f"(d[0]), "+f"(d[1]), "+f"(d[2]), "+f"(d[3])
        : "r"(a[0]), "r"(a[1]), "r"(a[2]), "r"(a[3]), "r"(b[0]), "r"(b[1]));
}
__device__ __forceinline__ void ldsm4(u32& r0, u32& r1, u32& r2, u32& r3, u32 addr){
    asm volatile("ldmatrix.sync.aligned.m8n8.x4.shared.b16 {%0,%1,%2,%3},[%4];"
        : "=r"(r0), "=r"(r1), "=r"(r2), "=r"(r3) : "r"(addr));
}
__device__ __forceinline__ void cp16(u32 sdst, const void* gsrc){
    asm volatile("cp.async.cg.shared.global [%0], [%1], 16;" :: "r"(sdst), "l"(gsrc));
}

// ============ K0a: WqT + WoT transposes + softplus ==========================
__global__ void k0a_prep(const float* __restrict__ Wq, const float* __restrict__ Wo,
                         const float* __restrict__ daa){
    int stride = gridDim.x * blockDim.x;
    int gid = blockIdx.x * blockDim.x + threadIdx.x;
    for (int idx = gid; idx < 5*384*48; idx += stride){
        int g = idx/(384*48), rem = idx%(384*48), o = rem/48, i = rem%48;
        g_WqT[(g*48+i)*384+o] = Wq[idx];
    }
    for (int idx = gid; idx < 5*48*384; idx += stride){
        int g = idx/(48*384), rem = idx%(48*384), o = rem/384, i = rem%384;
        g_WoT[(g*384+i)*48+o] = Wo[idx];
    }
    if (gid < 8){
        float x = daa[gid];
        g_sp[gid] = (x > 20.f) ? x : log1pf(expf(x));
    }
}

// ============ K0b: WkvT transpose ===========================================
__global__ void k0b_prep(const float* __restrict__ Wkv){
    int stride = gridDim.x * blockDim.x;
    int gid = blockIdx.x * blockDim.x + threadIdx.x;
    for (int idx = gid; idx < 5*768*48; idx += stride){
        int g = idx/(768*48), rem = idx%(768*48), o = rem/48, i = rem%48;
        g_WkvT[(g*48+i)*768+o] = Wkv[idx];
    }
}

// ============ K2x: rmsnorm + reorder -> xfeat [row][544] (bf16) =============
__global__ void __launch_bounds__(256) k2x_xfeat(const float* __restrict__ hidden,
                                                 const float* __restrict__ lnw){
    extern __shared__ float sx[];
    float* rows = sx;               // 16*768
    float* rsq  = sx + 16*768;      // 16
    int b = blockIdx.y, q0 = blockIdx.x*16, t = threadIdx.x;
    const float* hrow = hidden + (size_t)(b*NQ+q0)*768;
    for (int idx = t; idx < 16*768; idx += 256) rows[idx] = hrow[idx];
    __syncthreads();
    { int r = t>>4, sub = t&15; float s = 0.f;
      for (int e = sub; e < 768; e += 16){ float v = rows[r*768+e]; s += v*v; }
      s += __shfl_xor_sync(~0u, s, 1);
      s += __shfl_xor_sync(~0u, s, 2);
      s += __shfl_xor_sync(~0u, s, 4);
      s += __shfl_xor_sync(~0u, s, 8);
      if (sub == 0) rsq[r] = rsqrtf(s*(1.f/48.f) + 1e-6f);
    }
    __syncthreads();
    __nv_bfloat16* dst = g_xfeat + (size_t)(b*NQ+q0)*DX;
    for (int idx = t; idx < 16*DX; idx += 256){
        int r = idx/DX, d = idx - r*DX;
        float val;
        if (d < DF){
            int js = d/48, in = d - js*48;
            val = rows[r*768 + in*16 + c_comps[js]] * rsq[r] * lnw[in];
        } else val = (d == DF) ? 1.f : 0.f;
        dst[idx] = __float2bfloat16(val);
    }
}

// ========== K1a: kv projection; grid (ktile, s, b) -> kfeatT/vtmp ===========
__global__ void __launch_bounds__(256) k1a_kv(const float* __restrict__ vision,
                                              const float* __restrict__ bkv){
    extern __shared__ float sm1[];
    float* xT = sm1;            // [(c*48+in)][key16] pad 18
    int b = blockIdx.z, s = blockIdx.y, k0 = blockIdx.x*16, t = threadIdx.x;

    for (int idx = t; idx < 16*768; idx += 256){
        int key = idx/768, e = idx - key*768, in = e>>4, c = e&15;
        xT[(c*48+in)*18 + key] = vision[((size_t)(b*NK + k0 + key))*768 + e];
    }
    __syncthreads();

    const float INVS = 0.051031036307982884f;  // 1/sqrt(384)
    const int GR[16] = {0,1,1,1,1,2,2,2,2,2,2,3,3,3,3,4};

    int o = t + 256*s;
    float bias = bkv[o];
    const float* wb = g_WkvT + o;
    for (int kt = 0; kt < 4; kt++){
        u64 acc[2][16];
        #pragma unroll
        for (int kp = 0; kp < 2; kp++){
            acc[kp][0] = pk2(bias, bias);
            #pragma unroll
            for (int c = 1; c < 16; c++) acc[kp][c] = 0ull;
        }
        #pragma unroll 4
        for (int in = 0; in < 48; in++){
            float w0 = wb[(0*48+in)*768], w1 = wb[(1*48+in)*768];
            float w2 = wb[(2*48+in)*768], w3 = wb[(3*48+in)*768];
            float w4 = wb[(4*48+in)*768];
            u64 wv[5] = {pk2(w0,w0), pk2(w1,w1), pk2(w2,w2), pk2(w3,w3), pk2(w4,w4)};
            #pragma unroll
            for (int c = 0; c < 16; c++){
                const float* xp = xT + (c*48+in)*18 + kt*4;
                acc[0][c] = f2fma(*(const u64*)(xp    ), wv[GR[c]], acc[0][c]);
                acc[1][c] = f2fma(*(const u64*)(xp + 2), wv[GR[c]], acc[1][c]);
            }
        }
        if (o < 384){
            int h = o/48, i = o - h*48;
            float sp = g_sp[h], spc = sp*(2.f/48.f);
            size_t rb = (size_t)((b*HH+h)*NK + k0 + kt*4)*DFP;
            const int IC[8] = {0,2,3,4,8,9,10,14};
            #pragma unroll
            for (int js = 0; js < 8; js++)
                #pragma unroll
                for (int kp = 0; kp < 2; kp++){
                    float lo, hi; upk2(acc[kp][IC[js]], lo, hi);
                    g_kfeatT[rb + (size_t)(2*kp  )*DFP + js*48+i] = lo*INVS;
                    g_kfeatT[rb + (size_t)(2*kp+1)*DFP + js*48+i] = hi*INVS;
                }
            const int PC[3] = {11,12,13};
            #pragma unroll
            for (int jp = 0; jp < 3; jp++)
                #pragma unroll
                for (int kp = 0; kp < 2; kp++){
                    float lo, hi; upk2(acc[kp][PC[jp]], lo, hi);
                    g_kfeatT[rb + (size_t)(2*kp  )*DFP + 384+jp*48+i] = lo*spc;
                    g_kfeatT[rb + (size_t)(2*kp+1)*DFP + 384+jp*48+i] = hi*spc;
                }
        } else {
            int vc = o - 384, h = vc/48, i = vc - h*48;
            // contiguous per (b,h,ktile) block: [i*16+c][key16]
            float* vb = g_vtmp + ((size_t)((b*HH+h)*16 + (k0>>4)))*12288 + i*256 + kt*4;
            #pragma unroll
            for (int c = 0; c < 16; c++){
                *(u64*)&vb[c*16]     = acc[0][c];
                *(u64*)&vb[c*16 + 2] = acc[1][c];
            }
        }
    }
}

// ========== K1b: vprojT via cp.async pipelined subtiles =====================
__global__ void __launch_bounds__(256) k1b_vproj(){
    extern __shared__ float sm2[];
    float* w_s = sm2;             // 11520
    float* v_s = sm2 + 11520;     // 2 * 6144
    int sl = blockIdx.x, h = blockIdx.y, b = blockIdx.z, t = threadIdx.x;

    for (int idx = t; idx < 11520; idx += 256){
        int g = idx/2304, r = idx - g*2304;
        w_s[idx] = g_WoT[(g*384 + h*48)*48 + r];
    }
    int j = sl*256 + t;
    int o48 = j % 48, c = j / 48;
    int g = c_grade[c];
    const float* Vg = g_vtmp + (size_t)((b*HH+h)*16)*12288;
    u32 sb = smem_u32(v_s);
    const float* wp = w_s + g*2304 + o48;

    // stage subtile s (8 keys): ktile = s>>1, half = s&1
    {   // s = 0
        const float* src = Vg;
        #pragma unroll
        for (int it = 0; it < 6; it++){
            int idx = t + 256*it;            // 1536 chunks of 16B
            int row = idx>>1, part = idx&1;
            cp16(sb + (u32)(row*8 + part*4)*4, src + row*16 + part*4);
        }
        asm volatile("cp.async.commit_group;" ::: "memory");
    }

    for (int s = 0; s < 32; s++){
        asm volatile("cp.async.wait_group 0;" ::: "memory");
        __syncthreads();
        if (s + 1 < 32){
            const float* src = Vg + (size_t)((s+1)>>1)*12288 + ((s+1)&1)*8;
            int buf = (s+1)&1;
            #pragma unroll
            for (int it = 0; it < 6; it++){
                int idx = t + 256*it;
                int row = idx>>1, part = idx&1;
                cp16(sb + (u32)(buf*6144 + row*8 + part*4)*4, src + row*16 + part*4);
            }
            asm volatile("cp.async.commit_group;" ::: "memory");
        } else {
            asm volatile("cp.async.commit_group;" ::: "memory");
        }
        const float* vp0 = v_s + (s&1)*6144 + c*8;
        u64 acc[4] = {0ull, 0ull, 0ull, 0ull};
        #pragma unroll 8
        for (int i = 0; i < 48; i++){
            float w = wp[i*48];
            u64 w2 = pk2(w, w);
            const float* vp = vp0 + i*128;
            acc[0] = f2fma(*(const u64*)(vp    ), w2, acc[0]);
            acc[1] = f2fma(*(const u64*)(vp + 2), w2, acc[1]);
            acc[2] = f2fma(*(const u64*)(vp + 4), w2, acc[2]);
            acc[3] = f2fma(*(const u64*)(vp + 6), w2, acc[3]);
        }
        u32 r4[4];
        #pragma unroll
        for (int kp = 0; kp < 4; kp++){
            float lo, hi; upk2(acc[kp], lo, hi);
            r4[kp] = bf2(lo, hi);
        }
        __nv_bfloat16* dst = g_vprojT + (size_t)(b*768 + o48*16 + c)*2048
                           + h*256 + (s>>1)*16 + (s&1)*8;
        *(uint4*)dst = *(const uint4*)r4;
        __syncthreads();
    }
}

// ======= K2m: M[b,h][k][544] (bf16) — 512 CTAs, 32 keys each ================
__global__ void __launch_bounds__(256) k2m_M(const float* __restrict__ bq){
    __shared__ float kfT[48*34];   // [j][key32] pad 34
    __shared__ float ws [48*49];   // [j][c] pad 49
    __shared__ float mT [48*34];   // [c][key32] pad 34
    __shared__ float kb32[32];
    __shared__ float ss32[32];
    int kt0 = blockIdx.x*32, h = blockIdx.y, b = blockIdx.z, t = threadIdx.x;
    size_t kbase = (size_t)((b*HH+h)*NK) + kt0;
    if (t < 32) ss32[t] = 0.f;

    for (int js = 0; js < 11; js++){
        int g = c_cg[js];
        __syncthreads();
        #pragma unroll
        for (int r = 0; r < 6; r++){
            int idx = t + 256*r;                // 48*32 = 1536
            if (idx < 1536){
                int k = idx/48, j = idx - k*48;
                kfT[j*34 + k] = g_kfeatT[(kbase + k)*DFP + js*48 + j];
            }
        }
        #pragma unroll
        for (int r = 0; r < 9; r++){
            int idx = t + 256*r;                // 2304
            if (idx < 2304){
                int c = idx/48, j = idx - c*48;
                ws[j*49 + c] = g_WqT[(g*48+c)*384 + h*48 + j];
            }
        }
        __syncthreads();
        if (js == 0 && t < 32){
            float s = 0.f;
            #pragma unroll 8
            for (int j = 0; j < 48; j++) s += bq[h*48+j]*kfT[j*34 + t];
            kb32[t] = s;
        }
        if (js >= 8 && t < 32){
            float s = 0.f;
            #pragma unroll 8
            for (int j = 0; j < 48; j++){ float v = kfT[j*34 + t]; s += v*v; }
            ss32[t] += s;
        }
        #pragma unroll
        for (int r = 0; r < 3; r++){
            int o = t + 256*r;                  // 768 = 48c * 16 keypairs
            int c = o >> 4, kp = o & 15;
            u64 acc = 0ull;
            #pragma unroll 8
            for (int j = 0; j < 48; j++){
                float w = ws[j*49 + c];
                acc = f2fma(*(const u64*)&kfT[j*34 + 2*kp], pk2(w, w), acc);
            }
            *(u64*)&mT[c*34 + 2*kp] = acc;
        }
        __syncthreads();
        #pragma unroll
        for (int r = 0; r < 6; r++){
            int idx = t + 256*r;
            if (idx < 1536){
                int k = idx/48, c = idx - k*48;
                g_M[(kbase + k)*DX + js*48 + c] = __float2bfloat16(mT[c*34 + k]);
            }
        }
    }
    __syncthreads();
    float sp = g_sp[h];
    #pragma unroll
    for (int r = 0; r < 2; r++){
        int idx = t + 256*r;                    // 32*16 = 512
        int k = idx >> 4, cc = idx & 15;
        float v = (cc == 0) ? (kb32[k] - (12.f/sp)*ss32[k]) : 0.f;
        g_M[(kbase + k)*DX + DF + cc] = __float2bfloat16(v);
    }
}

// ============ bf16 GEMM core: 64 rows x 256 cols, ldmatrix + mma16816 =======
#define AROW 20
#define BOFF 1280
#define BUFU 6400

__device__ __forceinline__ void gemm_chunk(u32 base, float acc[4][4][4],
                                           int wid, u32 aofs, u32 bofs){
    #pragma unroll
    for (int k16 = 0; k16 < 2; k16++){
        int ko = k16*8;
        u32 au[4][4];
        #pragma unroll
        for (int mt = 0; mt < 4; mt++)
            ldsm4(au[mt][0], au[mt][1], au[mt][2], au[mt][3],
                  base + (u32)(mt*16*AROW + ko)*4 + aofs);
        u32 bu[4][2];
        ldsm4(bu[0][0], bu[0][1], bu[1][0], bu[1][1],
              base + (u32)(BOFF + wid*32*AROW + ko)*4 + bofs);
        ldsm4(bu[2][0], bu[2][1], bu[3][0], bu[3][1],
              base + (u32)(BOFF + (wid*32+16)*AROW + ko)*4 + bofs);
        #pragma unroll
        for (int mt = 0; mt < 4; mt++)
            #pragma unroll
            for (int nt8 = 0; nt8 < 4; nt8++)
                mma16816(acc[mt][nt8], au[mt], bu[nt8]);
    }
}

__device__ __forceinline__ void stage_tile(int t, u32 sb, const __nv_bfloat16* Ag,
                                           const __nv_bfloat16* Bg, int kc, int stride){
    { int row = t>>2, seg = t&3;
      cp16(sb + (u32)(row*AROW + seg*4)*4, Ag + (size_t)row*stride + kc*32 + seg*8); }
    #pragma unroll
    for (int it = 0; it < 4; it++){
        int i = t + 256*it, row = i>>2, seg = i&3;
        cp16(sb + (u32)(BOFF + row*AROW + seg*4)*4, Bg + (size_t)row*stride + kc*32 + seg*8);
    }
    asm volatile("cp.async.commit_group;" ::: "memory");
}

// ===================== K2b: bf16 mma logits + softmax ======================
__global__ void __launch_bounds__(256, 2) k2b_logits(){
    extern __shared__ u32 smp[];
    float* red  = (float*)(smp + 3*BUFU);   // 512
    float* rmax = red + 512;
    float* rsum = rmax + 64;
    int t = threadIdx.x, wid = t>>5, lane = t&31;
    int g = lane>>2, t4 = lane&3;
    int qt = blockIdx.x, h = blockIdx.y, b = blockIdx.z;

    u32 aofs = (u32)((((lane&7) + ((lane>>3)&1)*8)*AROW + ((lane>>4)&1)*4)*4);
    u32 bofs = (u32)(((((lane>>4)&1)*8 + (lane&7))*AROW + ((lane>>3)&1)*4)*4);

    const __nv_bfloat16* Ag = g_xfeat + (size_t)(b*NQ + qt*64)*DX;
    const __nv_bfloat16* Bg = g_M     + (size_t)((b*HH+h)*NK)*DX;
    u32 sb = smem_u32(smp);

    float acc[4][4][4];
    #pragma unroll
    for (int mt = 0; mt < 4; mt++)
        #pragma unroll
        for (int nt8 = 0; nt8 < 4; nt8++)
            #pragma unroll
            for (int r = 0; r < 4; r++) acc[mt][nt8][r] = 0.f;

    stage_tile(t, sb, Ag, Bg, 0, DX);
    stage_tile(t, sb + BUFU*4, Ag, Bg, 1, DX);
    for (int kc = 0; kc < 17; kc++){
        asm volatile("cp.async.wait_group 1;" ::: "memory");
        __syncthreads();
        if (kc + 2 < 17)
            stage_tile(t, sb + (u32)(((kc+2)%3)*BUFU)*4, Ag, Bg, kc+2, DX);
        else
            asm volatile("cp.async.commit_group;" ::: "memory");
        gemm_chunk(sb + (u32)((kc%3)*BUFU)*4, acc, wid, aofs, bofs);
    }

    __syncthreads();
    #pragma unroll
    for (int mt = 0; mt < 4; mt++)
        #pragma unroll
        for (int i = 0; i < 2; i++){
            float m = -1e30f;
            #pragma unroll
            for (int nt8 = 0; nt8 < 4; nt8++)
                m = fmaxf(m, fmaxf(acc[mt][nt8][2*i], acc[mt][nt8][2*i+1]));
            m = fmaxf(m, __shfl_xor_sync(~0u, m, 1));
            m = fmaxf(m, __shfl_xor_sync(~0u, m, 2));
            if (t4 == 0) red[(mt*16 + g + i*8)*8 + wid] = m;
        }
    __syncthreads();
    if (t < 64){
        float m = red[t*8];
        #pragma unroll
        for (int j = 1; j < 8; j++) m = fmaxf(m, red[t*8+j]);
        rmax[t] = m;
    }
    __syncthreads();
    #pragma unroll
    for (int mt = 0; mt < 4; mt++)
        #pragma unroll
        for (int i = 0; i < 2; i++){
            float mm = rmax[mt*16 + g + i*8];
            float s = 0.f;
            #pragma unroll
            for (int nt8 = 0; nt8 < 4; nt8++){
                float e0 = __expf(acc[mt][nt8][2*i]   - mm);
                float e1 = __expf(acc[mt][nt8][2*i+1] - mm);
                acc[mt][nt8][2*i] = e0; acc[mt][nt8][2*i+1] = e1;
                s += e0 + e1;
            }
            s += __shfl_xor_sync(~0u, s, 1);
            s += __shfl_xor_sync(~0u, s, 2);
            if (t4 == 0) red[(mt*16 + g + i*8)*8 + wid] = s;
        }
    __syncthreads();
    if (t < 64){
        float s = red[t*8];
        #pragma unroll
        for (int j = 1; j < 8; j++) s += red[t*8+j];
        rsum[t] = 1.f/s;
    }
    __syncthreads();
    #pragma unroll
    for (int mt = 0; mt < 4; mt++)
        #pragma unroll
        for (int i = 0; i < 2; i++){
            int row = mt*16 + g + i*8;
            float inv = rsum[row];
            __nv_bfloat16* dst = g_attn + (size_t)(b*NQ + qt*64 + row)*2048 + h*NK + wid*32;
            #pragma unroll
            for (int nt8 = 0; nt8 < 4; nt8++)
                *(u32*)(dst + nt8*8 + t4*2) = bf2(acc[mt][nt8][2*i]*inv,
                                                  acc[mt][nt8][2*i+1]*inv);
        }
}

// ===================== K3: bf16 mma attn @ vprojT + residual ================
__global__ void __launch_bounds__(256, 2) k3_av(const float* __restrict__ hidden,
                                                const float* __restrict__ bo,
                                                float* __restrict__ out){
    extern __shared__ u32 smp[];
    int t = threadIdx.x, wid = t>>5, lane = t&31;
    int g = lane>>2, t4 = lane&3;
    int nt = blockIdx.x, qt = blockIdx.y, b = blockIdx.z;

    u32 aofs = (u32)((((lane&7) + ((lane>>3)&1)*8)*AROW + ((lane>>4)&1)*4)*4);
    u32 bofs = (u32)(((((lane>>4)&1)*8 + (lane&7))*AROW + ((lane>>3)&1)*4)*4);

    const __nv_bfloat16* Ag = g_attn   + (size_t)(b*NQ + qt*64)*2048;
    const __nv_bfloat16* Bg = g_vprojT + (size_t)(b*768 + nt*256)*2048;
    u32 sb = smem_u32(smp);

    float acc[4][4][4];
    #pragma unroll
    for (int mt = 0; mt < 4; mt++)
        #pragma unroll
        for (int nt8 = 0; nt8 < 4; nt8++)
            #pragma unroll
            for (int r = 0; r < 4; r++) acc[mt][nt8][r] = 0.f;

    stage_tile(t, sb, Ag, Bg, 0, 2048);
    stage_tile(t, sb + BUFU*4, Ag, Bg, 1, 2048);
    for (int kc = 0; kc < 64; kc++){
        asm volatile("cp.async.wait_group 1;" ::: "memory");
        __syncthreads();
        if (kc + 2 < 64)
            stage_tile(t, sb + (u32)(((kc+2)%3)*BUFU)*4, Ag, Bg, kc+2, 2048);
        else
            asm volatile("cp.async.commit_group;" ::: "memory");
        gemm_chunk(sb + (u32)((kc%3)*BUFU)*4, acc, wid, aofs, bofs);
    }

    #pragma unroll
    for (int mt = 0; mt < 4; mt++)
        #pragma unroll
        for (int i = 0; i < 2; i++){
            int row = qt*64 + mt*16 + g + i*8;
            const float* hb = hidden + (size_t)(b*NQ + row)*768;
            float*       ob = out    + (size_t)(b*NQ + row)*768;
            #pragma unroll
            for (int nt8 = 0; nt8 < 4; nt8++){
                int col = nt*256 + wid*32 + nt8*8 + t4*2;
                float2 hv = *(const float2*)(hb + col);
                float vx = acc[mt][nt8][2*i]   + hv.x;
                float vy = acc[mt][nt8][2*i+1] + hv.y;
                if ((col & 15) == 0) vx += bo[col >> 4];
                *(float2*)(ob + col) = make_float2(vx, vy);
            }
        }
}

// ===========================================================================
extern "C" void kernel_launch(void* const* d_in, const int* in_sizes, int n_in,
                              void* d_out, int out_size){
    const float* hidden = (const float*)d_in[0];
    const float* vision = (const float*)d_in[1];
    const float* lnw    = (const float*)d_in[2];
    const float* Wq     = (const float*)d_in[3];
    const float* bq     = (const float*)d_in[4];
    const float* Wkv    = (const float*)d_in[5];
    const float* bkv    = (const float*)d_in[6];
    const float* Wo     = (const float*)d_in[7];
    const float* bo     = (const float*)d_in[8];
    const float* daa    = (const float*)d_in[9];
    float* out = (float*)d_out;

    const int s2x = (16*768 + 16)*4;
    const int s1a = (768*18)*4;
    const int s1b = (11520 + 2*6144)*4;               // 95232
    const int s2b = (3*BUFU)*4 + (512 + 64 + 64)*4;   // 79360
    const int s3  = (3*BUFU)*4;                        // 76800
    cudaFuncSetAttribute(k2x_xfeat, cudaFuncAttributeMaxDynamicSharedMemorySize, s2x);
    cudaFuncSetAttribute(k1a_kv,    cudaFuncAttributeMaxDynamicSharedMemorySize, s1a);
    cudaFuncSetAttribute(k1b_vproj, cudaFuncAttributeMaxDynamicSharedMemorySize, s1b);
    cudaFuncSetAttribute(k2b_logits,cudaFuncAttributeMaxDynamicSharedMemorySize, s2b);
    cudaFuncSetAttribute(k3_av,     cudaFuncAttributeMaxDynamicSharedMemorySize, s3);

    k0a_prep  <<<64, 256>>>(Wq, Wo, daa);                      // launch 0
    k0b_prep  <<<64, 256>>>(Wkv);                              // launch 1
    k2x_xfeat <<<dim3(NQ/16, BB), 256, s2x>>>(hidden, lnw);    // launch 2
    k1a_kv    <<<dim3(NK/16, 3, BB), 256, s1a>>>(vision, bkv); // launch 3 (profiled)
    k1b_vproj <<<dim3(3, HH, BB), 256, s1b>>>();               // launch 4
    k2m_M     <<<dim3(NK/32, HH, BB), 256>>>(bq);              // launch 5
    k2b_logits<<<dim3(NQ/64, HH, BB), 256, s2b>>>();           // launch 6
    k3_av     <<<dim3(3, NQ/64, BB), 256, s3>>>(hidden, bo, out); // launch 7
}